// round 12
// baseline (speedup 1.0000x reference)
#include <cuda_runtime.h>
#include <cuda_fp16.h>
#include <cuda_bf16.h>
#include <math.h>
#include <stdint.h>

#define NEDGE 524288
#define NNODE 32768
#define NGR   8
#define NLOC  4096
#define FIN   128
#define HID   512

#define OUT_MC    80
#define OUT_OL    81
#define OUT_SLOG  82
#define OUT_OA    65618

// ---- scratch ----
__device__ __half         g_Ah[NNODE * 512];     // [hi(agg|x)(256) | lo(agg|x)(256)] fp16
__device__ __half         g_Bh[512 * 256];       // Bh[n][k]: fp16(W=[W1;W2]), K=256
__device__ __nv_bfloat16  g_hb[NNODE * HID];     // h in bf16 (32MB)
__device__ float g_slp[4 * NNODE * 2];           // s_logits partials per N-CTA
__device__ float g_s[NNODE * 2];
__device__ int   g_cnt[NNODE + 1];
__device__ int   g_offs[NNODE + 1];
__device__ int   g_cursor[NNODE];
__device__ float2 g_edge[NEDGE];                 // sorted {src(bits), w}
__device__ float g_d[NNODE];
__device__ float g_accum[NGR * 4];
__device__ float g_oaraw[NGR * 4];
__device__ float g_out[NGR * 2 * HID];

__device__ __forceinline__ float wredx(float v) {
#pragma unroll
    for (int o = 16; o; o >>= 1) v += __shfl_xor_sync(0xffffffffu, v, o);
    return v;
}

#define SMEM_SWZ(o) ((o) ^ (((o) >> 3) & 0x70))

__device__ __forceinline__ uint32_t smem_u32(const void* p) {
    return (uint32_t)__cvta_generic_to_shared(p);
}
__device__ __forceinline__ void cp16s(uint32_t saddr, const void* g) {
    asm volatile("cp.async.cg.shared.global [%0], [%1], 16;"
                 :: "r"(saddr), "l"(g) : "memory");
}
__device__ __forceinline__ void ldsm4(uint32_t* r, uint32_t a) {
    asm volatile("ldmatrix.sync.aligned.m8n8.x4.shared.b16 {%0,%1,%2,%3}, [%4];"
                 : "=r"(r[0]), "=r"(r[1]), "=r"(r[2]), "=r"(r[3]) : "r"(a));
}
__device__ __forceinline__ void ldsm2(uint32_t* r, uint32_t a) {
    asm volatile("ldmatrix.sync.aligned.m8n8.x2.shared.b16 {%0,%1}, [%2];"
                 : "=r"(r[0]), "=r"(r[1]) : "r"(a));
}
#define MMA_F16(d, a, b)                                                      \
    asm volatile(                                                             \
        "mma.sync.aligned.m16n8k16.row.col.f32.f16.f16.f32 "                  \
        "{%0,%1,%2,%3},{%4,%5,%6,%7},{%8,%9},{%0,%1,%2,%3};"                  \
        : "+f"((d)[0]), "+f"((d)[1]), "+f"((d)[2]), "+f"((d)[3])              \
        : "r"((a)[0]), "r"((a)[1]), "r"((a)[2]), "r"((a)[3]),                 \
          "r"((b)[0]), "r"((b)[1]))

// ---------------- zero scratch ----------------
__global__ void zero_kernel(float* __restrict__ dout) {
    int i = blockIdx.x * 256 + threadIdx.x;
    if (i < NNODE + 1) g_cnt[i] = 0;
    if (i < NNODE)     g_d[i] = 0.f;
    if (i < NGR * 2 * HID) g_out[i] = 0.f;
    if (i < NGR * 4) { g_accum[i] = 0.f; g_oaraw[i] = 0.f; }
    if (i < 2) dout[OUT_MC + i] = 0.f;
}

// ---------------- count by dst + degree by src (2 edges/thread) ---------
__global__ void count_kernel(const int* __restrict__ ei,
                             const float* __restrict__ ew) {
    int g = blockIdx.x * 256 + threadIdx.x;
    int e = g * 2;
    if (e >= NEDGE) return;
    int2   s2 = *(const int2*)&ei[e];
    int2   d2 = *(const int2*)&ei[NEDGE + e];
    float2 w2 = *(const float2*)&ew[e];
    atomicAdd(&g_cnt[d2.x], 1);
    atomicAdd(&g_cnt[d2.y], 1);
    atomicAdd(&g_d[s2.x], w2.x);
    atomicAdd(&g_d[s2.y], w2.y);
}

// ---------------- exclusive scan (1 block, 1024 thr) ----------------
__global__ void scan_kernel() {
    __shared__ int sm[1024];
    int tid = threadIdx.x;
    int base = tid * 32;
    int sum = 0;
#pragma unroll
    for (int i = 0; i < 32; i++) sum += g_cnt[base + i];
    sm[tid] = sum;
    __syncthreads();
    for (int o = 1; o < 1024; o <<= 1) {
        int v = (tid >= o) ? sm[tid - o] : 0;
        __syncthreads();
        sm[tid] += v;
        __syncthreads();
    }
    int run = sm[tid] - sum;
#pragma unroll
    for (int i = 0; i < 32; i++) {
        int c = g_cnt[base + i];
        g_offs[base + i] = run;
        g_cursor[base + i] = run;
        run += c;
    }
    if (tid == 1023) g_offs[NNODE] = run;
}

// ---------------- scatter edges sorted by dst (2 edges/thread) ----------
__global__ void scatter_kernel(const int* __restrict__ ei,
                               const float* __restrict__ ew) {
    int g = blockIdx.x * 256 + threadIdx.x;
    int e = g * 2;
    if (e >= NEDGE) return;
    int2   s2 = *(const int2*)&ei[e];
    int2   d2 = *(const int2*)&ei[NEDGE + e];
    float2 w2 = *(const float2*)&ew[e];
    int p0 = atomicAdd(&g_cursor[d2.x], 1);
    int p1 = atomicAdd(&g_cursor[d2.y], 1);
    g_edge[p0] = make_float2(__int_as_float(s2.x), w2.x);
    g_edge[p1] = make_float2(__int_as_float(s2.y), w2.y);
}

// ------- fused prep: agg (blocks 0-4095) | cvtX (4096-8191) | cvtB ------
__global__ void prep_kernel(const float* __restrict__ x,
                            const float* __restrict__ W1,
                            const float* __restrict__ W2) {
    int blk = blockIdx.x;
    if (blk < 4096) {
        // agg -> fp16 hi/lo (warp per dst node)
        int gwarp = (blk * 256 + threadIdx.x) >> 5;
        int lane  = threadIdx.x & 31;
        int s0 = g_offs[gwarp], s1 = g_offs[gwarp + 1];
        const float4* x4 = (const float4*)x;
        float4 acc = make_float4(0.f, 0.f, 0.f, 0.f);
        int e = s0;
        for (; e + 4 <= s1; e += 4) {
            float2 e0 = g_edge[e],     e1 = g_edge[e + 1];
            float2 e2 = g_edge[e + 2], e3 = g_edge[e + 3];
            int sn0 = __float_as_int(e0.x), sn1 = __float_as_int(e1.x);
            int sn2 = __float_as_int(e2.x), sn3 = __float_as_int(e3.x);
            float4 v0 = x4[sn0 * 32 + lane];
            float4 v1 = x4[sn1 * 32 + lane];
            float4 v2 = x4[sn2 * 32 + lane];
            float4 v3 = x4[sn3 * 32 + lane];
            acc.x += e0.y * v0.x; acc.y += e0.y * v0.y; acc.z += e0.y * v0.z; acc.w += e0.y * v0.w;
            acc.x += e1.y * v1.x; acc.y += e1.y * v1.y; acc.z += e1.y * v1.z; acc.w += e1.y * v1.w;
            acc.x += e2.y * v2.x; acc.y += e2.y * v2.y; acc.z += e2.y * v2.z; acc.w += e2.y * v2.w;
            acc.x += e3.y * v3.x; acc.y += e3.y * v3.y; acc.z += e3.y * v3.z; acc.w += e3.y * v3.w;
        }
        for (; e < s1; e++) {
            float2 ee = g_edge[e];
            int sn = __float_as_int(ee.x);
            float4 v = x4[sn * 32 + lane];
            acc.x += ee.y * v.x; acc.y += ee.y * v.y; acc.z += ee.y * v.z; acc.w += ee.y * v.w;
        }
        __half h[4], l[4];
        float vv[4] = { acc.x, acc.y, acc.z, acc.w };
#pragma unroll
        for (int j = 0; j < 4; j++) {
            h[j] = __float2half_rn(vv[j]);
            l[j] = __float2half_rn(vv[j] - __half2float(h[j]));
        }
        size_t rb = (size_t)gwarp * 512 + lane * 4;
        *(uint2*)&g_Ah[rb]       = *(uint2*)h;
        *(uint2*)&g_Ah[rb + 256] = *(uint2*)l;
    } else if (blk < 8192) {
        // x half of A_ext: hi[128..255], lo[384..511]
        int idx = (blk - 4096) * 256 + threadIdx.x;
        int row = idx >> 5;
        int c4  = (idx & 31) * 4;
        float4 v = *(const float4*)&x[(size_t)row * 128 + c4];
        __half h[4], l[4];
        float vv[4] = { v.x, v.y, v.z, v.w };
#pragma unroll
        for (int j = 0; j < 4; j++) {
            h[j] = __float2half_rn(vv[j]);
            l[j] = __float2half_rn(vv[j] - __half2float(h[j]));
        }
        size_t rb = (size_t)row * 512;
        *(uint2*)&g_Ah[rb + 128 + c4] = *(uint2*)h;
        *(uint2*)&g_Ah[rb + 384 + c4] = *(uint2*)l;
    } else {
        // Bh[n][k] = fp16 of W = [W1;W2], K=256
        int idx = (blk - 8192) * 256 + threadIdx.x;
        int n = idx >> 8;
        int r = idx & 255;
        float v = (r < 128) ? W1[(size_t)r * 512 + n]
                            : W2[(size_t)(r - 128) * 512 + n];
        g_Bh[(size_t)n * 256 + r] = __float2half_rn(v);
    }
}

// ------- h(bf16) = relu(A_ext @ Bh^T + b); also s_logits partials --------
// 128x128 tile, BK=64, 8 stages (hi x4, lo x4; B reused), 3-stage ring.
#define GB_SMEM 98304

__global__ __launch_bounds__(256) void gemm_h_bf(const float* __restrict__ bias,
                                                 const float* __restrict__ Wp) {
    extern __shared__ char dsm[];
    __shared__ float slacc[128][2];
    uint32_t base = smem_u32(dsm);
    uint32_t Ao[3] = { base,         base + 16384, base + 32768 };
    uint32_t Bo[3] = { base + 49152, base + 65536, base + 81920 };

    int tid  = threadIdx.x;
    int lane = tid & 31;
    int wid  = tid >> 5;
    int warp_m = wid & 1;
    int warp_n = wid >> 1;
    int bm = blockIdx.y * 128;
    int bn = blockIdx.x * 128;

    if (tid < 256) slacc[tid >> 1][tid & 1] = 0.f;

    float cacc[4][4][4];
#pragma unroll
    for (int i = 0; i < 4; i++)
#pragma unroll
        for (int j = 0; j < 4; j++)
#pragma unroll
            for (int r = 0; r < 4; r++) cacc[i][j][r] = 0.f;

    auto load_stage = [&](int s, int buf) {
        int kA = ((s & 3) << 6) + ((s >> 2) << 8);   // hi cols 0-255, lo cols 256-511
        int kB = (s & 3) << 6;                        // B reused across segments
#pragma unroll
        for (int t = 0; t < 4; t++) {
            int id  = tid + t * 256;
            int r   = id >> 3;
            int c16 = id & 7;
            uint32_t off = SMEM_SWZ((uint32_t)(r * 128 + c16 * 16));
            cp16s(Ao[buf] + off, &g_Ah[(size_t)(bm + r) * 512 + kA + c16 * 8]);
        }
#pragma unroll
        for (int t = 0; t < 4; t++) {
            int id  = tid + t * 256;
            int r   = id >> 3;
            int c16 = id & 7;
            uint32_t off = SMEM_SWZ((uint32_t)(r * 128 + c16 * 16));
            cp16s(Bo[buf] + off, &g_Bh[(size_t)(bn + r) * 256 + kB + c16 * 8]);
        }
        asm volatile("cp.async.commit_group;" ::: "memory");
    };

    int a_row  = warp_m * 64 + (lane & 15);
    int a_csel = ((lane >> 4) & 1) * 16;
    int b_row  = warp_n * 32 + (lane & 7);
    int b_csel = (lane & 8) ? 16 : 0;

    load_stage(0, 0);
    load_stage(1, 1);

    for (int s = 0; s < 8; s++) {
        if (s + 2 < 8) {
            load_stage(s + 2, (s + 2) % 3);
            asm volatile("cp.async.wait_group 2;" ::: "memory");
        } else if (s + 1 < 8) {
            asm volatile("cp.async.wait_group 1;" ::: "memory");
        } else {
            asm volatile("cp.async.wait_group 0;" ::: "memory");
        }
        __syncthreads();

        uint32_t As = Ao[s % 3];
        uint32_t Bs = Bo[s % 3];
#pragma unroll
        for (int k = 0; k < 4; k++) {
            int kbA = k * 32 + a_csel;
            int kbB = k * 32 + b_csel;
            uint32_t a[4][4], b[4][2];
#pragma unroll
            for (int mi = 0; mi < 4; mi++) {
                uint32_t addr = As + SMEM_SWZ((uint32_t)((a_row + mi * 16) * 128 + kbA));
                ldsm4(a[mi], addr);
            }
#pragma unroll
            for (int ni = 0; ni < 4; ni++) {
                uint32_t addr = Bs + SMEM_SWZ((uint32_t)((b_row + ni * 8) * 128 + kbB));
                ldsm2(b[ni], addr);
            }
#pragma unroll
            for (int mi = 0; mi < 4; mi++)
#pragma unroll
                for (int ni = 0; ni < 4; ni++)
                    MMA_F16(cacc[mi][ni], a[mi], b[ni]);
        }
        __syncthreads();
    }

    // epilogue: bias + relu -> bf16 h; per-row partial s_logits over 128 cols
    const float2* Wp2 = (const float2*)Wp;
#pragma unroll
    for (int mi = 0; mi < 4; mi++) {
        int r0loc = warp_m * 64 + mi * 16 + (lane >> 2);
        int row0  = bm + r0loc;
        float p00 = 0.f, p01 = 0.f, p10 = 0.f, p11 = 0.f;
#pragma unroll
        for (int ni = 0; ni < 4; ni++) {
            int gcol = bn + warp_n * 32 + ni * 8 + 2 * (lane & 3);
            float b0 = bias[gcol], b1 = bias[gcol + 1];
            float v00 = fmaxf(cacc[mi][ni][0] + b0, 0.f);
            float v01 = fmaxf(cacc[mi][ni][1] + b1, 0.f);
            float v10 = fmaxf(cacc[mi][ni][2] + b0, 0.f);
            float v11 = fmaxf(cacc[mi][ni][3] + b1, 0.f);
            __nv_bfloat162 h0, h1;
            h0.x = __float2bfloat16(v00); h0.y = __float2bfloat16(v01);
            h1.x = __float2bfloat16(v10); h1.y = __float2bfloat16(v11);
            *(__nv_bfloat162*)&g_hb[(size_t)row0 * HID + gcol]       = h0;
            *(__nv_bfloat162*)&g_hb[(size_t)(row0 + 8) * HID + gcol] = h1;
            float2 w0 = Wp2[gcol], w1 = Wp2[gcol + 1];
            p00 += v00 * w0.x + v01 * w1.x;
            p01 += v00 * w0.y + v01 * w1.y;
            p10 += v10 * w0.x + v11 * w1.x;
            p11 += v10 * w0.y + v11 * w1.y;
        }
#pragma unroll
        for (int o = 1; o <= 2; o <<= 1) {
            p00 += __shfl_xor_sync(0xffffffffu, p00, o);
            p01 += __shfl_xor_sync(0xffffffffu, p01, o);
            p10 += __shfl_xor_sync(0xffffffffu, p10, o);
            p11 += __shfl_xor_sync(0xffffffffu, p11, o);
        }
        if ((lane & 3) == 0) {
            atomicAdd(&slacc[r0loc][0], p00);
            atomicAdd(&slacc[r0loc][1], p01);
            atomicAdd(&slacc[r0loc + 8][0], p10);
            atomicAdd(&slacc[r0loc + 8][1], p11);
        }
    }
    __syncthreads();
    if (tid < 256) {
        int r = tid >> 1, j = tid & 1;
        g_slp[((size_t)blockIdx.x * NNODE + bm + r) * 2 + j] = slacc[r][j];
    }
}

// ------- fused: s_logits sum + softmax + ss/den + pooled features --------
__global__ __launch_bounds__(256) void s_pool_kernel(const float* __restrict__ bp,
                                                     float* __restrict__ dout) {
    __shared__ float psm[8][1024];
    __shared__ float red[8][4];
    int tid  = threadIdx.x;
    int wip  = tid >> 5;
    int lane = tid & 31;
    float bp0 = bp[0], bp1 = bp[1];

    float2 pA[8], pB[8];
#pragma unroll
    for (int i = 0; i < 8; i++) { pA[i] = make_float2(0.f, 0.f); pB[i] = make_float2(0.f, 0.f); }
    float ss00 = 0.f, ss01 = 0.f, ss11 = 0.f, den = 0.f;

    int nbase = blockIdx.x * 32 + wip * 4;
#pragma unroll
    for (int nn = 0; nn < 4; nn++) {
        int node = nbase + nn;
        float s0 = 0.f, s1 = 0.f;
        if (lane == 0) {
            float d0 = bp0, d1 = bp1;
#pragma unroll
            for (int i = 0; i < 4; i++) {
                float2 p = *(const float2*)&g_slp[((size_t)i * NNODE + node) * 2];
                d0 += p.x; d1 += p.y;
            }
            dout[OUT_SLOG + node * 2]     = d0;
            dout[OUT_SLOG + node * 2 + 1] = d1;
            float m = fmaxf(d0, d1);
            float e0 = expf(d0 - m), e1 = expf(d1 - m);
            float inv = 1.f / (e0 + e1);
            s0 = e0 * inv; s1 = e1 * inv;
            g_s[node * 2] = s0; g_s[node * 2 + 1] = s1;
            float dn = g_d[node];
            ss00 += s0 * s0; ss01 += s0 * s1; ss11 += s1 * s1;
            den  += dn * (s0 * s0 + s1 * s1);
        }
        s0 = __shfl_sync(0xffffffffu, s0, 0);
        s1 = __shfl_sync(0xffffffffu, s1, 0);
        const __nv_bfloat162* hrow = (const __nv_bfloat162*)(g_hb + (size_t)node * HID);
#pragma unroll
        for (int i = 0; i < 8; i++) {
            __nv_bfloat162 hp = hrow[lane + 32 * i];
            float hx = __bfloat162float(hp.x);
            float hy = __bfloat162float(hp.y);
            pA[i].x += s0 * hx; pA[i].y += s0 * hy;
            pB[i].x += s1 * hx; pB[i].y += s1 * hy;
        }
    }
#pragma unroll
    for (int i = 0; i < 8; i++) {
        *(float2*)&psm[wip][2 * lane + 64 * i]       = pA[i];
        *(float2*)&psm[wip][512 + 2 * lane + 64 * i] = pB[i];
    }
    if (lane == 0) {
        red[wip][0] = ss00; red[wip][1] = ss01; red[wip][2] = ss11; red[wip][3] = den;
    }
    __syncthreads();

    int b = nbase >> 12;
    for (int f = tid; f < 1024; f += 256) {
        float t = 0.f;
#pragma unroll
        for (int w = 0; w < 8; w++) t += psm[w][f];
        atomicAdd(&g_out[b * 1024 + f], t);
    }
    if (tid < 4) {
        float t = 0.f;
#pragma unroll
        for (int w = 0; w < 8; w++) t += red[w][tid];
        atomicAdd(&g_accum[b * 4 + tid], t);
    }
}

// ---------------- out_adj[b,c,k] = sum_e s[src,c]*w*s[dst,k] ------------
__global__ void oa_kernel(const int* __restrict__ ei,
                          const float* __restrict__ ew) {
    __shared__ float red[8][4];
    int e = blockIdx.x * 256 + threadIdx.x;
    int src = ei[e];
    int dst = ei[NEDGE + e];
    float w = ew[e];
    float ss0 = g_s[src * 2], ss1 = g_s[src * 2 + 1];
    float sd0 = g_s[dst * 2], sd1 = g_s[dst * 2 + 1];
    float v00 = ss0 * w * sd0, v01 = ss0 * w * sd1;
    float v10 = ss1 * w * sd0, v11 = ss1 * w * sd1;
    v00 = wredx(v00); v01 = wredx(v01); v10 = wredx(v10); v11 = wredx(v11);
    int wip = threadIdx.x >> 5;
    if ((threadIdx.x & 31) == 0) {
        red[wip][0] = v00; red[wip][1] = v01; red[wip][2] = v10; red[wip][3] = v11;
    }
    __syncthreads();
    if (threadIdx.x < 4) {
        int b = src >> 12;
        float t = 0.f;
#pragma unroll
        for (int w2 = 0; w2 < 8; w2++) t += red[w2][threadIdx.x];
        atomicAdd(&g_oaraw[b * 4 + threadIdx.x], t);
    }
}

// ------- fused tail: finalize + xm + h2 + logits (1 block per graph) -----
__global__ __launch_bounds__(512) void tail_kernel(const float* __restrict__ Wrel3,
                                                   const float* __restrict__ brel3,
                                                   const float* __restrict__ Wroot3,
                                                   const float* __restrict__ Wlin1,
                                                   const float* __restrict__ blin1,
                                                   const float* __restrict__ Wlin2,
                                                   const float* __restrict__ blin2,
                                                   float* __restrict__ dout) {
    __shared__ float so0[512], so1[512], sxm[512], sh2[512];
    __shared__ float soan[2];
    __shared__ float lg[10];
    int b = blockIdx.x;
    int tid = threadIdx.x;

    if (tid == 0) {
        float a00 = g_oaraw[b * 4 + 0], a01 = g_oaraw[b * 4 + 1];
        float a10 = g_oaraw[b * 4 + 2], a11 = g_oaraw[b * 4 + 3];
        float num = a00 + a11;
        float den = g_accum[b * 4 + 3];
        float mc = -(num / den);
        float ss00 = g_accum[b * 4 + 0], ss01 = g_accum[b * 4 + 1], ss11 = g_accum[b * 4 + 2];
        float nrm = sqrtf(ss00 * ss00 + 2.f * ss01 * ss01 + ss11 * ss11);
        const float q = 0.70710678118654752f;
        float n00 = ss00 / nrm - q, n01 = ss01 / nrm, n11 = ss11 / nrm - q;
        float ol = sqrtf(n00 * n00 + 2.f * n01 * n01 + n11 * n11);
        float d2_0 = sqrtf(a01) + 1e-15f;
        float d2_1 = sqrtf(a10) + 1e-15f;
        float oa01 = a01 / (d2_0 * d2_1);
        float oa10 = a10 / (d2_1 * d2_0);
        soan[0] = oa01; soan[1] = oa10;
        dout[OUT_OA + b * 4 + 0] = 0.f;
        dout[OUT_OA + b * 4 + 1] = oa01;
        dout[OUT_OA + b * 4 + 2] = oa10;
        dout[OUT_OA + b * 4 + 3] = 0.f;
        atomicAdd(&dout[OUT_MC], mc / (float)NGR);
        atomicAdd(&dout[OUT_OL], ol / (float)NGR);
    }
    so0[tid] = g_out[(b * 2 + 0) * HID + tid];
    so1[tid] = g_out[(b * 2 + 1) * HID + tid];
    __syncthreads();

    float oa01 = soan[0], oa10 = soan[1];
    float acc = 0.f;
    for (int k = 0; k < HID; k++) {
        float u = oa10 * so1[k] + oa01 * so0[k];
        float v = so0[k] + so1[k];
        acc += u * Wrel3[k * HID + tid] + v * Wroot3[k * HID + tid];
    }
    sxm[tid] = 0.5f * acc + brel3[tid];
    __syncthreads();

    float acc2 = 0.f;
    for (int k = 0; k < HID; k++)
        acc2 += sxm[k] * Wlin1[k * HID + tid];
    sh2[tid] = fmaxf(acc2 + blin1[tid], 0.f);
    __syncthreads();

    if (tid < 320) {
        int o = tid >> 5, lane = tid & 31;
        float a = 0.f;
        for (int k = lane; k < HID; k += 32)
            a += sh2[k] * Wlin2[k * 10 + o];
        a = wredx(a);
        if (lane == 0) lg[o] = a + blin2[o];
    }
    __syncthreads();
    if (tid == 0) {
        float m = lg[0];
#pragma unroll
        for (int i = 1; i < 10; i++) m = fmaxf(m, lg[i]);
        float sum = 0.f;
#pragma unroll
        for (int i = 0; i < 10; i++) sum += expf(lg[i] - m);
        float lse = logf(sum) + m;
#pragma unroll
        for (int i = 0; i < 10; i++) dout[b * 10 + i] = lg[i] - lse;
    }
}

extern "C" void kernel_launch(void* const* d_in, const int* in_sizes, int n_in,
                              void* d_out, int out_size) {
    const float* x       = (const float*)d_in[0];
    const int*   ei      = (const int*)d_in[1];   // int32 (JAX x64 disabled)
    const float* ew      = (const float*)d_in[3];
    const float* W_rel1  = (const float*)d_in[4];
    const float* b_rel1  = (const float*)d_in[5];
    const float* W_root1 = (const float*)d_in[6];
    const float* W_pool  = (const float*)d_in[7];
    const float* b_pool  = (const float*)d_in[8];
    const float* W_rel3  = (const float*)d_in[9];
    const float* b_rel3  = (const float*)d_in[10];
    const float* W_root3 = (const float*)d_in[11];
    const float* W_lin1  = (const float*)d_in[12];
    const float* b_lin1  = (const float*)d_in[13];
    const float* W_lin2  = (const float*)d_in[14];
    const float* b_lin2  = (const float*)d_in[15];
    float* out = (float*)d_out;

    static int smem_set = 0;
    if (!smem_set) {
        cudaFuncSetAttribute(gemm_h_bf, cudaFuncAttributeMaxDynamicSharedMemorySize,
                             GB_SMEM);
        smem_set = 1;
    }

    zero_kernel<<<129, 256>>>(out);
    count_kernel<<<NEDGE / 512, 256>>>(ei, ew);
    scan_kernel<<<1, 1024>>>();
    scatter_kernel<<<NEDGE / 512, 256>>>(ei, ew);
    prep_kernel<<<8704, 256>>>(x, W_rel1, W_root1);
    gemm_h_bf<<<dim3(HID / 128, NNODE / 128), 256, GB_SMEM>>>(b_rel1, W_pool);
    s_pool_kernel<<<NNODE / 32, 256>>>(b_pool, out);
    oa_kernel<<<NEDGE / 256, 256>>>(ei, ew);
    tail_kernel<<<NGR, 512>>>(W_rel3, b_rel3, W_root3, W_lin1, b_lin1,
                              W_lin2, b_lin2, out);
}

// round 13
// speedup vs baseline: 1.3496x; 1.3496x over previous
#include <cuda_runtime.h>
#include <cuda_fp16.h>
#include <cuda_bf16.h>
#include <math.h>
#include <stdint.h>

#define NEDGE 524288
#define NNODE 32768
#define NGR   8
#define NLOC  4096
#define FIN   128
#define HID   512

#define OUT_MC    80
#define OUT_OL    81
#define OUT_SLOG  82
#define OUT_OA    65618

// ---- scratch ----
__device__ __half         g_Ah[NNODE * 512];     // [hi(agg|x)(256) | lo(agg|x)(256)] fp16
__device__ __half         g_Bh[512 * 256];       // Bh[n][k]: fp16(W=[W1;W2]), K=256
__device__ __half         g_xh[NNODE * FIN];     // x in fp16 for the agg gather (8MB)
__device__ __nv_bfloat16  g_hb[NNODE * HID];     // h in bf16 (32MB)
__device__ float g_slp[4 * NNODE * 2];           // s_logits partials per N-CTA
__device__ float g_s[NNODE * 2];
__device__ int   g_cnt[NNODE];
__device__ int   g_offs[NNODE + 1];
__device__ int   g_cursor[NNODE];
__device__ int   g_bsum[128];
__device__ float2 g_edge[NEDGE];                 // sorted {src(bits), w}
__device__ float g_d[NNODE];
__device__ float g_accum[NGR * 4];
__device__ float g_oaraw[NGR * 4];
__device__ float g_out[NGR * 2 * HID];

__device__ __forceinline__ float wredx(float v) {
#pragma unroll
    for (int o = 16; o; o >>= 1) v += __shfl_xor_sync(0xffffffffu, v, o);
    return v;
}
__device__ __forceinline__ int iredx(int v) {
#pragma unroll
    for (int o = 16; o; o >>= 1) v += __shfl_xor_sync(0xffffffffu, v, o);
    return v;
}

#define SMEM_SWZ(o) ((o) ^ (((o) >> 3) & 0x70))

__device__ __forceinline__ uint32_t smem_u32(const void* p) {
    return (uint32_t)__cvta_generic_to_shared(p);
}
__device__ __forceinline__ void cp16s(uint32_t saddr, const void* g) {
    asm volatile("cp.async.cg.shared.global [%0], [%1], 16;"
                 :: "r"(saddr), "l"(g) : "memory");
}
__device__ __forceinline__ void ldsm4(uint32_t* r, uint32_t a) {
    asm volatile("ldmatrix.sync.aligned.m8n8.x4.shared.b16 {%0,%1,%2,%3}, [%4];"
                 : "=r"(r[0]), "=r"(r[1]), "=r"(r[2]), "=r"(r[3]) : "r"(a));
}
__device__ __forceinline__ void ldsm2(uint32_t* r, uint32_t a) {
    asm volatile("ldmatrix.sync.aligned.m8n8.x2.shared.b16 {%0,%1}, [%2];"
                 : "=r"(r[0]), "=r"(r[1]) : "r"(a));
}
#define MMA_F16(d, a, b)                                                      \
    asm volatile(                                                             \
        "mma.sync.aligned.m16n8k16.row.col.f32.f16.f16.f32 "                  \
        "{%0,%1,%2,%3},{%4,%5,%6,%7},{%8,%9},{%0,%1,%2,%3};"                  \
        : "+f"((d)[0]), "+f"((d)[1]), "+f"((d)[2]), "+f"((d)[3])              \
        : "r"((a)[0]), "r"((a)[1]), "r"((a)[2]), "r"((a)[3]),                 \
          "r"((b)[0]), "r"((b)[1]))

// ---------------- zero scratch ----------------
__global__ void zero_kernel(float* __restrict__ dout) {
    int i = blockIdx.x * 256 + threadIdx.x;
    if (i < NNODE) g_cnt[i] = 0;
    if (i < NNODE) g_d[i] = 0.f;
    if (i < NGR * 2 * HID) g_out[i] = 0.f;
    if (i < NGR * 4) { g_accum[i] = 0.f; g_oaraw[i] = 0.f; }
    if (i < 2) dout[OUT_MC + i] = 0.f;
}

// ------- fused: x->fp16 + A_ext x-half (4096 blks) | B->fp16 (512 blks) --
__global__ void cvtXB_kernel(const float* __restrict__ x,
                             const float* __restrict__ W1,
                             const float* __restrict__ W2) {
    int blk = blockIdx.x;
    if (blk < 4096) {
        int idx = blk * 256 + threadIdx.x;
        int row = idx >> 5;
        int c4  = (idx & 31) * 4;
        float4 v = *(const float4*)&x[(size_t)row * 128 + c4];
        __half h[4], l[4];
        float vv[4] = { v.x, v.y, v.z, v.w };
#pragma unroll
        for (int j = 0; j < 4; j++) {
            h[j] = __float2half_rn(vv[j]);
            l[j] = __float2half_rn(vv[j] - __half2float(h[j]));
        }
        size_t rb = (size_t)row * 512;
        *(uint2*)&g_Ah[rb + 128 + c4] = *(uint2*)h;
        *(uint2*)&g_Ah[rb + 384 + c4] = *(uint2*)l;
        *(uint2*)&g_xh[(size_t)row * 128 + c4] = *(uint2*)h;
    } else {
        int idx = (blk - 4096) * 256 + threadIdx.x;
        int n = idx >> 8;
        int r = idx & 255;
        float v = (r < 128) ? W1[(size_t)r * 512 + n]
                            : W2[(size_t)(r - 128) * 512 + n];
        g_Bh[(size_t)n * 256 + r] = __float2half_rn(v);
    }
}

// ---------------- count by dst + degree by src (2 edges/thread) ---------
__global__ void count_kernel(const int* __restrict__ ei,
                             const float* __restrict__ ew) {
    int g = blockIdx.x * 256 + threadIdx.x;
    int e = g * 2;
    if (e >= NEDGE) return;
    int2   s2 = *(const int2*)&ei[e];
    int2   d2 = *(const int2*)&ei[NEDGE + e];
    float2 w2 = *(const float2*)&ew[e];
    atomicAdd(&g_cnt[d2.x], 1);
    atomicAdd(&g_cnt[d2.y], 1);
    atomicAdd(&g_d[s2.x], w2.x);
    atomicAdd(&g_d[s2.y], w2.y);
}

// ---------------- scan phase A: 128 blocks, local exclusive scan --------
__global__ void scanA_kernel() {
    __shared__ int sm[256];
    int tid = threadIdx.x;
    int idx = blockIdx.x * 256 + tid;
    int v = g_cnt[idx];
    sm[tid] = v;
    __syncthreads();
#pragma unroll
    for (int o = 1; o < 256; o <<= 1) {
        int t = (tid >= o) ? sm[tid - o] : 0;
        __syncthreads();
        sm[tid] += t;
        __syncthreads();
    }
    int incl = sm[tid];
    g_offs[idx] = incl - v;   // local exclusive
    if (tid == 255) g_bsum[blockIdx.x] = incl;
}

// ---------------- scan phase C: add block offsets, write cursor ---------
__global__ void scanC_kernel() {
    __shared__ int soff;
    int tid = threadIdx.x;
    int blk = blockIdx.x;
    if (tid < 32) {
        int s = 0;
        for (int j = tid; j < blk; j += 32) s += g_bsum[j];
        s = iredx(s);
        if (tid == 0) soff = s;
    }
    __syncthreads();
    int idx = blk * 256 + tid;
    int val = g_offs[idx] + soff;
    g_offs[idx] = val;
    g_cursor[idx] = val;
    if (blk == 0 && tid == 0) g_offs[NNODE] = NEDGE;
}

// ---------------- scatter edges sorted by dst (2 edges/thread) ----------
__global__ void scatter_kernel(const int* __restrict__ ei,
                               const float* __restrict__ ew) {
    int g = blockIdx.x * 256 + threadIdx.x;
    int e = g * 2;
    if (e >= NEDGE) return;
    int2   s2 = *(const int2*)&ei[e];
    int2   d2 = *(const int2*)&ei[NEDGE + e];
    float2 w2 = *(const float2*)&ew[e];
    int p0 = atomicAdd(&g_cursor[d2.x], 1);
    int p1 = atomicAdd(&g_cursor[d2.y], 1);
    g_edge[p0] = make_float2(__int_as_float(s2.x), w2.x);
    g_edge[p1] = make_float2(__int_as_float(s2.y), w2.y);
}

// ---------------- agg (fp16 gather) -> fp16 hi/lo (warp per dst) --------
__global__ void agg_kernel() {
    int gwarp = (blockIdx.x * 256 + threadIdx.x) >> 5;
    int lane  = threadIdx.x & 31;
    int s0 = g_offs[gwarp], s1 = g_offs[gwarp + 1];
    const uint2* xh = (const uint2*)g_xh;
    float4 acc = make_float4(0.f, 0.f, 0.f, 0.f);
    int e = s0;
    for (; e + 4 <= s1; e += 4) {
        float2 e0 = g_edge[e],     e1 = g_edge[e + 1];
        float2 e2 = g_edge[e + 2], e3 = g_edge[e + 3];
        uint2 u0 = xh[__float_as_int(e0.x) * 32 + lane];
        uint2 u1 = xh[__float_as_int(e1.x) * 32 + lane];
        uint2 u2 = xh[__float_as_int(e2.x) * 32 + lane];
        uint2 u3 = xh[__float_as_int(e3.x) * 32 + lane];
        float2 a0 = __half22float2(*(__half2*)&u0.x), b0 = __half22float2(*(__half2*)&u0.y);
        float2 a1 = __half22float2(*(__half2*)&u1.x), b1 = __half22float2(*(__half2*)&u1.y);
        float2 a2 = __half22float2(*(__half2*)&u2.x), b2 = __half22float2(*(__half2*)&u2.y);
        float2 a3 = __half22float2(*(__half2*)&u3.x), b3 = __half22float2(*(__half2*)&u3.y);
        acc.x += e0.y * a0.x; acc.y += e0.y * a0.y; acc.z += e0.y * b0.x; acc.w += e0.y * b0.y;
        acc.x += e1.y * a1.x; acc.y += e1.y * a1.y; acc.z += e1.y * b1.x; acc.w += e1.y * b1.y;
        acc.x += e2.y * a2.x; acc.y += e2.y * a2.y; acc.z += e2.y * b2.x; acc.w += e2.y * b2.y;
        acc.x += e3.y * a3.x; acc.y += e3.y * a3.y; acc.z += e3.y * b3.x; acc.w += e3.y * b3.y;
    }
    for (; e < s1; e++) {
        float2 ee = g_edge[e];
        uint2 u = xh[__float_as_int(ee.x) * 32 + lane];
        float2 a = __half22float2(*(__half2*)&u.x), b = __half22float2(*(__half2*)&u.y);
        acc.x += ee.y * a.x; acc.y += ee.y * a.y; acc.z += ee.y * b.x; acc.w += ee.y * b.y;
    }
    __half h[4], l[4];
    float vv[4] = { acc.x, acc.y, acc.z, acc.w };
#pragma unroll
    for (int j = 0; j < 4; j++) {
        h[j] = __float2half_rn(vv[j]);
        l[j] = __float2half_rn(vv[j] - __half2float(h[j]));
    }
    size_t rb = (size_t)gwarp * 512 + lane * 4;
    *(uint2*)&g_Ah[rb]       = *(uint2*)h;
    *(uint2*)&g_Ah[rb + 256] = *(uint2*)l;
}

// ------- h(bf16) = relu(A_ext @ Bh^T + b); also s_logits partials --------
// 128x128 tile, BK=64, 8 stages (hi x4, lo x4; B reused), 3-stage ring.
#define GB_SMEM 98304

__global__ __launch_bounds__(256) void gemm_h_bf(const float* __restrict__ bias,
                                                 const float* __restrict__ Wp) {
    extern __shared__ char dsm[];
    __shared__ float slacc[128][2];
    uint32_t base = smem_u32(dsm);
    uint32_t Ao[3] = { base,         base + 16384, base + 32768 };
    uint32_t Bo[3] = { base + 49152, base + 65536, base + 81920 };

    int tid  = threadIdx.x;
    int lane = tid & 31;
    int wid  = tid >> 5;
    int warp_m = wid & 1;
    int warp_n = wid >> 1;
    int bm = blockIdx.y * 128;
    int bn = blockIdx.x * 128;

    if (tid < 256) slacc[tid >> 1][tid & 1] = 0.f;

    float cacc[4][4][4];
#pragma unroll
    for (int i = 0; i < 4; i++)
#pragma unroll
        for (int j = 0; j < 4; j++)
#pragma unroll
            for (int r = 0; r < 4; r++) cacc[i][j][r] = 0.f;

    auto load_stage = [&](int s, int buf) {
        int kA = ((s & 3) << 6) + ((s >> 2) << 8);   // hi cols 0-255, lo cols 256-511
        int kB = (s & 3) << 6;                        // B reused across segments
#pragma unroll
        for (int t = 0; t < 4; t++) {
            int id  = tid + t * 256;
            int r   = id >> 3;
            int c16 = id & 7;
            uint32_t off = SMEM_SWZ((uint32_t)(r * 128 + c16 * 16));
            cp16s(Ao[buf] + off, &g_Ah[(size_t)(bm + r) * 512 + kA + c16 * 8]);
        }
#pragma unroll
        for (int t = 0; t < 4; t++) {
            int id  = tid + t * 256;
            int r   = id >> 3;
            int c16 = id & 7;
            uint32_t off = SMEM_SWZ((uint32_t)(r * 128 + c16 * 16));
            cp16s(Bo[buf] + off, &g_Bh[(size_t)(bn + r) * 256 + kB + c16 * 8]);
        }
        asm volatile("cp.async.commit_group;" ::: "memory");
    };

    int a_row  = warp_m * 64 + (lane & 15);
    int a_csel = ((lane >> 4) & 1) * 16;
    int b_row  = warp_n * 32 + (lane & 7);
    int b_csel = (lane & 8) ? 16 : 0;

    load_stage(0, 0);
    load_stage(1, 1);

    for (int s = 0; s < 8; s++) {
        if (s + 2 < 8) {
            load_stage(s + 2, (s + 2) % 3);
            asm volatile("cp.async.wait_group 2;" ::: "memory");
        } else if (s + 1 < 8) {
            asm volatile("cp.async.wait_group 1;" ::: "memory");
        } else {
            asm volatile("cp.async.wait_group 0;" ::: "memory");
        }
        __syncthreads();

        uint32_t As = Ao[s % 3];
        uint32_t Bs = Bo[s % 3];
#pragma unroll
        for (int k = 0; k < 4; k++) {
            int kbA = k * 32 + a_csel;
            int kbB = k * 32 + b_csel;
            uint32_t a[4][4], b[4][2];
#pragma unroll
            for (int mi = 0; mi < 4; mi++) {
                uint32_t addr = As + SMEM_SWZ((uint32_t)((a_row + mi * 16) * 128 + kbA));
                ldsm4(a[mi], addr);
            }
#pragma unroll
            for (int ni = 0; ni < 4; ni++) {
                uint32_t addr = Bs + SMEM_SWZ((uint32_t)((b_row + ni * 8) * 128 + kbB));
                ldsm2(b[ni], addr);
            }
#pragma unroll
            for (int mi = 0; mi < 4; mi++)
#pragma unroll
                for (int ni = 0; ni < 4; ni++)
                    MMA_F16(cacc[mi][ni], a[mi], b[ni]);
        }
        __syncthreads();
    }

    // epilogue: bias + relu -> bf16 h; per-row partial s_logits over 128 cols
    const float2* Wp2 = (const float2*)Wp;
#pragma unroll
    for (int mi = 0; mi < 4; mi++) {
        int r0loc = warp_m * 64 + mi * 16 + (lane >> 2);
        int row0  = bm + r0loc;
        float p00 = 0.f, p01 = 0.f, p10 = 0.f, p11 = 0.f;
#pragma unroll
        for (int ni = 0; ni < 4; ni++) {
            int gcol = bn + warp_n * 32 + ni * 8 + 2 * (lane & 3);
            float b0 = bias[gcol], b1 = bias[gcol + 1];
            float v00 = fmaxf(cacc[mi][ni][0] + b0, 0.f);
            float v01 = fmaxf(cacc[mi][ni][1] + b1, 0.f);
            float v10 = fmaxf(cacc[mi][ni][2] + b0, 0.f);
            float v11 = fmaxf(cacc[mi][ni][3] + b1, 0.f);
            __nv_bfloat162 h0, h1;
            h0.x = __float2bfloat16(v00); h0.y = __float2bfloat16(v01);
            h1.x = __float2bfloat16(v10); h1.y = __float2bfloat16(v11);
            *(__nv_bfloat162*)&g_hb[(size_t)row0 * HID + gcol]       = h0;
            *(__nv_bfloat162*)&g_hb[(size_t)(row0 + 8) * HID + gcol] = h1;
            float2 w0 = Wp2[gcol], w1 = Wp2[gcol + 1];
            p00 += v00 * w0.x + v01 * w1.x;
            p01 += v00 * w0.y + v01 * w1.y;
            p10 += v10 * w0.x + v11 * w1.x;
            p11 += v10 * w0.y + v11 * w1.y;
        }
#pragma unroll
        for (int o = 1; o <= 2; o <<= 1) {
            p00 += __shfl_xor_sync(0xffffffffu, p00, o);
            p01 += __shfl_xor_sync(0xffffffffu, p01, o);
            p10 += __shfl_xor_sync(0xffffffffu, p10, o);
            p11 += __shfl_xor_sync(0xffffffffu, p11, o);
        }
        if ((lane & 3) == 0) {
            atomicAdd(&slacc[r0loc][0], p00);
            atomicAdd(&slacc[r0loc][1], p01);
            atomicAdd(&slacc[r0loc + 8][0], p10);
            atomicAdd(&slacc[r0loc + 8][1], p11);
        }
    }
    __syncthreads();
    if (tid < 256) {
        int r = tid >> 1, j = tid & 1;
        g_slp[((size_t)blockIdx.x * NNODE + bm + r) * 2 + j] = slacc[r][j];
    }
}

// ------- fused: s_logits sum + softmax + ss/den + pooled features --------
__global__ __launch_bounds__(256) void s_pool_kernel(const float* __restrict__ bp,
                                                     float* __restrict__ dout) {
    __shared__ float psm[8][1024];
    __shared__ float red[8][4];
    int tid  = threadIdx.x;
    int wip  = tid >> 5;
    int lane = tid & 31;
    float bp0 = bp[0], bp1 = bp[1];

    float2 pA[8], pB[8];
#pragma unroll
    for (int i = 0; i < 8; i++) { pA[i] = make_float2(0.f, 0.f); pB[i] = make_float2(0.f, 0.f); }
    float ss00 = 0.f, ss01 = 0.f, ss11 = 0.f, den = 0.f;

    int nbase = blockIdx.x * 32 + wip * 4;
#pragma unroll
    for (int nn = 0; nn < 4; nn++) {
        int node = nbase + nn;
        float s0 = 0.f, s1 = 0.f;
        if (lane == 0) {
            float d0 = bp0, d1 = bp1;
#pragma unroll
            for (int i = 0; i < 4; i++) {
                float2 p = *(const float2*)&g_slp[((size_t)i * NNODE + node) * 2];
                d0 += p.x; d1 += p.y;
            }
            dout[OUT_SLOG + node * 2]     = d0;
            dout[OUT_SLOG + node * 2 + 1] = d1;
            float m = fmaxf(d0, d1);
            float e0 = expf(d0 - m), e1 = expf(d1 - m);
            float inv = 1.f / (e0 + e1);
            s0 = e0 * inv; s1 = e1 * inv;
            g_s[node * 2] = s0; g_s[node * 2 + 1] = s1;
            float dn = g_d[node];
            ss00 += s0 * s0; ss01 += s0 * s1; ss11 += s1 * s1;
            den  += dn * (s0 * s0 + s1 * s1);
        }
        s0 = __shfl_sync(0xffffffffu, s0, 0);
        s1 = __shfl_sync(0xffffffffu, s1, 0);
        const __nv_bfloat162* hrow = (const __nv_bfloat162*)(g_hb + (size_t)node * HID);
#pragma unroll
        for (int i = 0; i < 8; i++) {
            __nv_bfloat162 hp = hrow[lane + 32 * i];
            float hx = __bfloat162float(hp.x);
            float hy = __bfloat162float(hp.y);
            pA[i].x += s0 * hx; pA[i].y += s0 * hy;
            pB[i].x += s1 * hx; pB[i].y += s1 * hy;
        }
    }
#pragma unroll
    for (int i = 0; i < 8; i++) {
        *(float2*)&psm[wip][2 * lane + 64 * i]       = pA[i];
        *(float2*)&psm[wip][512 + 2 * lane + 64 * i] = pB[i];
    }
    if (lane == 0) {
        red[wip][0] = ss00; red[wip][1] = ss01; red[wip][2] = ss11; red[wip][3] = den;
    }
    __syncthreads();

    int b = nbase >> 12;
    for (int f = tid; f < 1024; f += 256) {
        float t = 0.f;
#pragma unroll
        for (int w = 0; w < 8; w++) t += psm[w][f];
        atomicAdd(&g_out[b * 1024 + f], t);
    }
    if (tid < 4) {
        float t = 0.f;
#pragma unroll
        for (int w = 0; w < 8; w++) t += red[w][tid];
        atomicAdd(&g_accum[b * 4 + tid], t);
    }
}

// ---------------- out_adj[b,c,k] = sum_e s[src,c]*w*s[dst,k] ------------
__global__ void oa_kernel(const int* __restrict__ ei,
                          const float* __restrict__ ew) {
    __shared__ float red[8][4];
    int e = blockIdx.x * 256 + threadIdx.x;
    int src = ei[e];
    int dst = ei[NEDGE + e];
    float w = ew[e];
    float ss0 = g_s[src * 2], ss1 = g_s[src * 2 + 1];
    float sd0 = g_s[dst * 2], sd1 = g_s[dst * 2 + 1];
    float v00 = ss0 * w * sd0, v01 = ss0 * w * sd1;
    float v10 = ss1 * w * sd0, v11 = ss1 * w * sd1;
    v00 = wredx(v00); v01 = wredx(v01); v10 = wredx(v10); v11 = wredx(v11);
    int wip = threadIdx.x >> 5;
    if ((threadIdx.x & 31) == 0) {
        red[wip][0] = v00; red[wip][1] = v01; red[wip][2] = v10; red[wip][3] = v11;
    }
    __syncthreads();
    if (threadIdx.x < 4) {
        int b = src >> 12;
        float t = 0.f;
#pragma unroll
        for (int w2 = 0; w2 < 8; w2++) t += red[w2][threadIdx.x];
        atomicAdd(&g_oaraw[b * 4 + threadIdx.x], t);
    }
}

// ------- fused tail: finalize + xm + h2 + logits (1 block per graph) -----
__global__ __launch_bounds__(512) void tail_kernel(const float* __restrict__ Wrel3,
                                                   const float* __restrict__ brel3,
                                                   const float* __restrict__ Wroot3,
                                                   const float* __restrict__ Wlin1,
                                                   const float* __restrict__ blin1,
                                                   const float* __restrict__ Wlin2,
                                                   const float* __restrict__ blin2,
                                                   float* __restrict__ dout) {
    __shared__ float so0[512], so1[512], sxm[512], sh2[512];
    __shared__ float soan[2];
    __shared__ float lg[10];
    int b = blockIdx.x;
    int tid = threadIdx.x;

    if (tid == 0) {
        float a00 = g_oaraw[b * 4 + 0], a01 = g_oaraw[b * 4 + 1];
        float a10 = g_oaraw[b * 4 + 2], a11 = g_oaraw[b * 4 + 3];
        float num = a00 + a11;
        float den = g_accum[b * 4 + 3];
        float mc = -(num / den);
        float ss00 = g_accum[b * 4 + 0], ss01 = g_accum[b * 4 + 1], ss11 = g_accum[b * 4 + 2];
        float nrm = sqrtf(ss00 * ss00 + 2.f * ss01 * ss01 + ss11 * ss11);
        const float q = 0.70710678118654752f;
        float n00 = ss00 / nrm - q, n01 = ss01 / nrm, n11 = ss11 / nrm - q;
        float ol = sqrtf(n00 * n00 + 2.f * n01 * n01 + n11 * n11);
        float d2_0 = sqrtf(a01) + 1e-15f;
        float d2_1 = sqrtf(a10) + 1e-15f;
        float oa01 = a01 / (d2_0 * d2_1);
        float oa10 = a10 / (d2_1 * d2_0);
        soan[0] = oa01; soan[1] = oa10;
        dout[OUT_OA + b * 4 + 0] = 0.f;
        dout[OUT_OA + b * 4 + 1] = oa01;
        dout[OUT_OA + b * 4 + 2] = oa10;
        dout[OUT_OA + b * 4 + 3] = 0.f;
        atomicAdd(&dout[OUT_MC], mc / (float)NGR);
        atomicAdd(&dout[OUT_OL], ol / (float)NGR);
    }
    so0[tid] = g_out[(b * 2 + 0) * HID + tid];
    so1[tid] = g_out[(b * 2 + 1) * HID + tid];
    __syncthreads();

    float oa01 = soan[0], oa10 = soan[1];
    float acc = 0.f;
    for (int k = 0; k < HID; k++) {
        float u = oa10 * so1[k] + oa01 * so0[k];
        float v = so0[k] + so1[k];
        acc += u * Wrel3[k * HID + tid] + v * Wroot3[k * HID + tid];
    }
    sxm[tid] = 0.5f * acc + brel3[tid];
    __syncthreads();

    float acc2 = 0.f;
    for (int k = 0; k < HID; k++)
        acc2 += sxm[k] * Wlin1[k * HID + tid];
    sh2[tid] = fmaxf(acc2 + blin1[tid], 0.f);
    __syncthreads();

    if (tid < 320) {
        int o = tid >> 5, lane = tid & 31;
        float a = 0.f;
        for (int k = lane; k < HID; k += 32)
            a += sh2[k] * Wlin2[k * 10 + o];
        a = wredx(a);
        if (lane == 0) lg[o] = a + blin2[o];
    }
    __syncthreads();
    if (tid == 0) {
        float m = lg[0];
#pragma unroll
        for (int i = 1; i < 10; i++) m = fmaxf(m, lg[i]);
        float sum = 0.f;
#pragma unroll
        for (int i = 0; i < 10; i++) sum += expf(lg[i] - m);
        float lse = logf(sum) + m;
#pragma unroll
        for (int i = 0; i < 10; i++) dout[b * 10 + i] = lg[i] - lse;
    }
}

extern "C" void kernel_launch(void* const* d_in, const int* in_sizes, int n_in,
                              void* d_out, int out_size) {
    const float* x       = (const float*)d_in[0];
    const int*   ei      = (const int*)d_in[1];   // int32 (JAX x64 disabled)
    const float* ew      = (const float*)d_in[3];
    const float* W_rel1  = (const float*)d_in[4];
    const float* b_rel1  = (const float*)d_in[5];
    const float* W_root1 = (const float*)d_in[6];
    const float* W_pool  = (const float*)d_in[7];
    const float* b_pool  = (const float*)d_in[8];
    const float* W_rel3  = (const float*)d_in[9];
    const float* b_rel3  = (const float*)d_in[10];
    const float* W_root3 = (const float*)d_in[11];
    const float* W_lin1  = (const float*)d_in[12];
    const float* b_lin1  = (const float*)d_in[13];
    const float* W_lin2  = (const float*)d_in[14];
    const float* b_lin2  = (const float*)d_in[15];
    float* out = (float*)d_out;

    static int smem_set = 0;
    if (!smem_set) {
        cudaFuncSetAttribute(gemm_h_bf, cudaFuncAttributeMaxDynamicSharedMemorySize,
                             GB_SMEM);
        smem_set = 1;
    }

    zero_kernel<<<129, 256>>>(out);
    count_kernel<<<NEDGE / 512, 256>>>(ei, ew);
    cvtXB_kernel<<<4608, 256>>>(x, W_rel1, W_root1);
    scanA_kernel<<<128, 256>>>();
    scanC_kernel<<<128, 256>>>();
    scatter_kernel<<<NEDGE / 512, 256>>>(ei, ew);
    agg_kernel<<<NNODE / 8, 256>>>();
    gemm_h_bf<<<dim3(HID / 128, NNODE / 128), 256, GB_SMEM>>>(b_rel1, W_pool);
    s_pool_kernel<<<NNODE / 32, 256>>>(b_pool, out);
    oa_kernel<<<NEDGE / 256, 256>>>(ei, ew);
    tail_kernel<<<NGR, 512>>>(W_rel3, b_rel3, W_root3, W_lin1, b_lin1,
                              W_lin2, b_lin2, out);
}

// round 14
// speedup vs baseline: 1.4428x; 1.0691x over previous
#include <cuda_runtime.h>
#include <cuda_fp16.h>
#include <cuda_bf16.h>
#include <math.h>
#include <stdint.h>

#define NEDGE 524288
#define NNODE 32768
#define NGR   8
#define NLOC  4096
#define FIN   128
#define HID   512

#define OUT_MC    80
#define OUT_OL    81
#define OUT_SLOG  82
#define OUT_OA    65618

// ---- scratch ----
__device__ __half g_Ah[NNODE * 512];     // [hi(agg|x)(256) | lo(agg|x)(256)] fp16
__device__ __half g_Bh[512 * 256];       // Bh[n][k]: fp16(W=[W1;W2]), K=256
__device__ __half g_xh[NNODE * FIN];     // x in fp16 for the agg gather
__device__ float g_s[NNODE * 2];
__device__ int   g_cnt[NNODE];
__device__ int   g_offs[NNODE + 1];
__device__ int   g_cursor[NNODE];
__device__ int   g_bsum[128];
__device__ float2 g_edge[NEDGE];         // sorted {src(bits), w}
__device__ float g_d[NNODE];
__device__ float g_accum[NGR * 4];
__device__ float g_oaraw[NGR * 4];
__device__ float g_out[NGR * 2 * HID];

__device__ __forceinline__ float wredx(float v) {
#pragma unroll
    for (int o = 16; o; o >>= 1) v += __shfl_xor_sync(0xffffffffu, v, o);
    return v;
}
__device__ __forceinline__ int iredx(int v) {
#pragma unroll
    for (int o = 16; o; o >>= 1) v += __shfl_xor_sync(0xffffffffu, v, o);
    return v;
}

#define SMEM_SWZ(o) ((o) ^ (((o) >> 3) & 0x70))

__device__ __forceinline__ uint32_t smem_u32(const void* p) {
    return (uint32_t)__cvta_generic_to_shared(p);
}
__device__ __forceinline__ void cp16s(uint32_t saddr, const void* g) {
    asm volatile("cp.async.cg.shared.global [%0], [%1], 16;"
                 :: "r"(saddr), "l"(g) : "memory");
}
__device__ __forceinline__ void ldsm4(uint32_t* r, uint32_t a) {
    asm volatile("ldmatrix.sync.aligned.m8n8.x4.shared.b16 {%0,%1,%2,%3}, [%4];"
                 : "=r"(r[0]), "=r"(r[1]), "=r"(r[2]), "=r"(r[3]) : "r"(a));
}
__device__ __forceinline__ void ldsm2(uint32_t* r, uint32_t a) {
    asm volatile("ldmatrix.sync.aligned.m8n8.x2.shared.b16 {%0,%1}, [%2];"
                 : "=r"(r[0]), "=r"(r[1]) : "r"(a));
}
#define MMA_F16(d, a, b)                                                      \
    asm volatile(                                                             \
        "mma.sync.aligned.m16n8k16.row.col.f32.f16.f16.f32 "                  \
        "{%0,%1,%2,%3},{%4,%5,%6,%7},{%8,%9},{%0,%1,%2,%3};"                  \
        : "+f"((d)[0]), "+f"((d)[1]), "+f"((d)[2]), "+f"((d)[3])              \
        : "r"((a)[0]), "r"((a)[1]), "r"((a)[2]), "r"((a)[3]),                 \
          "r"((b)[0]), "r"((b)[1]))

// ---------------- zero scratch ----------------
__global__ void zero_kernel(float* __restrict__ dout) {
    int i = blockIdx.x * 256 + threadIdx.x;
    if (i < NNODE) g_cnt[i] = 0;
    if (i < NNODE) g_d[i] = 0.f;
    if (i < NGR * 2 * HID) g_out[i] = 0.f;
    if (i < NGR * 4) { g_accum[i] = 0.f; g_oaraw[i] = 0.f; }
    if (i < 2) dout[OUT_MC + i] = 0.f;
}

// --- fused prep: cvtX (0-4095) | cvtB (4096-4607) | count (4608-5631) ---
__global__ void prep_kernel(const float* __restrict__ x,
                            const float* __restrict__ W1,
                            const float* __restrict__ W2,
                            const int* __restrict__ ei,
                            const float* __restrict__ ew) {
    int blk = blockIdx.x;
    if (blk < 4096) {
        int idx = blk * 256 + threadIdx.x;
        int row = idx >> 5;
        int c4  = (idx & 31) * 4;
        float4 v = *(const float4*)&x[(size_t)row * 128 + c4];
        __half h[4], l[4];
        float vv[4] = { v.x, v.y, v.z, v.w };
#pragma unroll
        for (int j = 0; j < 4; j++) {
            h[j] = __float2half_rn(vv[j]);
            l[j] = __float2half_rn(vv[j] - __half2float(h[j]));
        }
        size_t rb = (size_t)row * 512;
        *(uint2*)&g_Ah[rb + 128 + c4] = *(uint2*)h;
        *(uint2*)&g_Ah[rb + 384 + c4] = *(uint2*)l;
        *(uint2*)&g_xh[(size_t)row * 128 + c4] = *(uint2*)h;
    } else if (blk < 4608) {
        int idx = (blk - 4096) * 256 + threadIdx.x;
        int n = idx >> 8;
        int r = idx & 255;
        float v = (r < 128) ? W1[(size_t)r * 512 + n]
                            : W2[(size_t)(r - 128) * 512 + n];
        g_Bh[(size_t)n * 256 + r] = __float2half_rn(v);
    } else {
        int g = (blk - 4608) * 256 + threadIdx.x;
        int e = g * 2;
        if (e >= NEDGE) return;
        int2   s2 = *(const int2*)&ei[e];
        int2   d2 = *(const int2*)&ei[NEDGE + e];
        float2 w2 = *(const float2*)&ew[e];
        atomicAdd(&g_cnt[d2.x], 1);
        atomicAdd(&g_cnt[d2.y], 1);
        atomicAdd(&g_d[s2.x], w2.x);
        atomicAdd(&g_d[s2.y], w2.y);
    }
}

// ---------------- scan phase A: 128 blocks, local exclusive scan --------
__global__ void scanA_kernel() {
    __shared__ int sm[256];
    int tid = threadIdx.x;
    int idx = blockIdx.x * 256 + tid;
    int v = g_cnt[idx];
    sm[tid] = v;
    __syncthreads();
#pragma unroll
    for (int o = 1; o < 256; o <<= 1) {
        int t = (tid >= o) ? sm[tid - o] : 0;
        __syncthreads();
        sm[tid] += t;
        __syncthreads();
    }
    int incl = sm[tid];
    g_offs[idx] = incl - v;
    if (tid == 255) g_bsum[blockIdx.x] = incl;
}

// ---------------- scan phase C: add block offsets, write cursor ---------
__global__ void scanC_kernel() {
    __shared__ int soff;
    int tid = threadIdx.x;
    int blk = blockIdx.x;
    if (tid < 32) {
        int s = 0;
        for (int j = tid; j < blk; j += 32) s += g_bsum[j];
        s = iredx(s);
        if (tid == 0) soff = s;
    }
    __syncthreads();
    int idx = blk * 256 + tid;
    int val = g_offs[idx] + soff;
    g_offs[idx] = val;
    g_cursor[idx] = val;
    if (blk == 0 && tid == 0) g_offs[NNODE] = NEDGE;
}

// ---------------- scatter edges sorted by dst (2 edges/thread) ----------
__global__ void scatter_kernel(const int* __restrict__ ei,
                               const float* __restrict__ ew) {
    int g = blockIdx.x * 256 + threadIdx.x;
    int e = g * 2;
    if (e >= NEDGE) return;
    int2   s2 = *(const int2*)&ei[e];
    int2   d2 = *(const int2*)&ei[NEDGE + e];
    float2 w2 = *(const float2*)&ew[e];
    int p0 = atomicAdd(&g_cursor[d2.x], 1);
    int p1 = atomicAdd(&g_cursor[d2.y], 1);
    g_edge[p0] = make_float2(__int_as_float(s2.x), w2.x);
    g_edge[p1] = make_float2(__int_as_float(s2.y), w2.y);
}

// ---------------- agg (fp16 gather) -> fp16 hi/lo (warp per dst) --------
__global__ void agg_kernel() {
    int gwarp = (blockIdx.x * 256 + threadIdx.x) >> 5;
    int lane  = threadIdx.x & 31;
    int s0 = g_offs[gwarp], s1 = g_offs[gwarp + 1];
    const uint2* xh = (const uint2*)g_xh;
    float4 acc = make_float4(0.f, 0.f, 0.f, 0.f);
    int e = s0;
    for (; e + 4 <= s1; e += 4) {
        float2 e0 = g_edge[e],     e1 = g_edge[e + 1];
        float2 e2 = g_edge[e + 2], e3 = g_edge[e + 3];
        uint2 u0 = xh[__float_as_int(e0.x) * 32 + lane];
        uint2 u1 = xh[__float_as_int(e1.x) * 32 + lane];
        uint2 u2 = xh[__float_as_int(e2.x) * 32 + lane];
        uint2 u3 = xh[__float_as_int(e3.x) * 32 + lane];
        float2 a0 = __half22float2(*(__half2*)&u0.x), b0 = __half22float2(*(__half2*)&u0.y);
        float2 a1 = __half22float2(*(__half2*)&u1.x), b1 = __half22float2(*(__half2*)&u1.y);
        float2 a2 = __half22float2(*(__half2*)&u2.x), b2 = __half22float2(*(__half2*)&u2.y);
        float2 a3 = __half22float2(*(__half2*)&u3.x), b3 = __half22float2(*(__half2*)&u3.y);
        acc.x += e0.y * a0.x; acc.y += e0.y * a0.y; acc.z += e0.y * b0.x; acc.w += e0.y * b0.y;
        acc.x += e1.y * a1.x; acc.y += e1.y * a1.y; acc.z += e1.y * b1.x; acc.w += e1.y * b1.y;
        acc.x += e2.y * a2.x; acc.y += e2.y * a2.y; acc.z += e2.y * b2.x; acc.w += e2.y * b2.y;
        acc.x += e3.y * a3.x; acc.y += e3.y * a3.y; acc.z += e3.y * b3.x; acc.w += e3.y * b3.y;
    }
    for (; e < s1; e++) {
        float2 ee = g_edge[e];
        uint2 u = xh[__float_as_int(ee.x) * 32 + lane];
        float2 a = __half22float2(*(__half2*)&u.x), b = __half22float2(*(__half2*)&u.y);
        acc.x += ee.y * a.x; acc.y += ee.y * a.y; acc.z += ee.y * b.x; acc.w += ee.y * b.y;
    }
    __half h[4], l[4];
    float vv[4] = { acc.x, acc.y, acc.z, acc.w };
#pragma unroll
    for (int j = 0; j < 4; j++) {
        h[j] = __float2half_rn(vv[j]);
        l[j] = __float2half_rn(vv[j] - __half2float(h[j]));
    }
    size_t rb = (size_t)gwarp * 512 + lane * 4;
    *(uint2*)&g_Ah[rb]       = *(uint2*)h;
    *(uint2*)&g_Ah[rb + 256] = *(uint2*)l;
}

// ===== mega GEMM: h tile in smem; fused s_logits+softmax+stats+pooling ===
// grid 256 (128 rows each), nb loop over 4 N-blocks of 128. h: 128x520 fp16.
#define HSTRIDE 520
#define HS_BYTES (128 * HSTRIDE * 2)       // 133120, 1024-aligned
#define GB_SMEM (HS_BYTES + 65536)

__global__ __launch_bounds__(256) void gemm_mega(const float* __restrict__ bias,
                                                 const float* __restrict__ Wp,
                                                 const float* __restrict__ bp,
                                                 float* __restrict__ dout) {
    extern __shared__ char dsm[];
    __half* hsm = (__half*)dsm;
    uint32_t base = smem_u32(dsm);
    uint32_t Ao[2] = { base + HS_BYTES,         base + HS_BYTES + 16384 };
    uint32_t Bo[2] = { base + HS_BYTES + 32768, base + HS_BYTES + 49152 };
    __shared__ float slacc[128][2];
    __shared__ float ssm[128][2];

    int tid  = threadIdx.x;
    int lane = tid & 31;
    int wid  = tid >> 5;
    int warp_m = wid & 1;
    int warp_n = wid >> 1;
    int bm = blockIdx.x * 128;

    if (tid < 128) { slacc[tid][0] = 0.f; slacc[tid][1] = 0.f; }

    int a_row  = warp_m * 64 + (lane & 15);
    int a_csel = ((lane >> 4) & 1) * 16;
    int b_row  = warp_n * 32 + (lane & 7);
    int b_csel = (lane & 8) ? 16 : 0;

    const float2* Wp2 = (const float2*)Wp;

    for (int nb = 0; nb < 4; nb++) {
        int bn = nb * 128;
        float cacc[4][4][4];
#pragma unroll
        for (int i = 0; i < 4; i++)
#pragma unroll
            for (int j = 0; j < 4; j++)
#pragma unroll
                for (int r = 0; r < 4; r++) cacc[i][j][r] = 0.f;

        auto load_stage = [&](int s, int buf) {
            int kA = ((s & 3) << 6) + ((s >> 2) << 8);
            int kB = (s & 3) << 6;
#pragma unroll
            for (int t = 0; t < 4; t++) {
                int id  = tid + t * 256;
                int r   = id >> 3;
                int c16 = id & 7;
                uint32_t off = SMEM_SWZ((uint32_t)(r * 128 + c16 * 16));
                cp16s(Ao[buf] + off, &g_Ah[(size_t)(bm + r) * 512 + kA + c16 * 8]);
            }
#pragma unroll
            for (int t = 0; t < 4; t++) {
                int id  = tid + t * 256;
                int r   = id >> 3;
                int c16 = id & 7;
                uint32_t off = SMEM_SWZ((uint32_t)(r * 128 + c16 * 16));
                cp16s(Bo[buf] + off, &g_Bh[(size_t)(bn + r) * 256 + kB + c16 * 8]);
            }
            asm volatile("cp.async.commit_group;" ::: "memory");
        };

        load_stage(0, 0);
        for (int s = 0; s < 8; s++) {
            if (s < 7) {
                load_stage(s + 1, (s + 1) & 1);
                asm volatile("cp.async.wait_group 1;" ::: "memory");
            } else {
                asm volatile("cp.async.wait_group 0;" ::: "memory");
            }
            __syncthreads();
            uint32_t As = Ao[s & 1];
            uint32_t Bs = Bo[s & 1];
#pragma unroll
            for (int k = 0; k < 4; k++) {
                int kbA = k * 32 + a_csel;
                int kbB = k * 32 + b_csel;
                uint32_t a[4][4], b[4][2];
#pragma unroll
                for (int mi = 0; mi < 4; mi++) {
                    uint32_t addr = As + SMEM_SWZ((uint32_t)((a_row + mi * 16) * 128 + kbA));
                    ldsm4(a[mi], addr);
                }
#pragma unroll
                for (int ni = 0; ni < 4; ni++) {
                    uint32_t addr = Bs + SMEM_SWZ((uint32_t)((b_row + ni * 8) * 128 + kbB));
                    ldsm2(b[ni], addr);
                }
#pragma unroll
                for (int mi = 0; mi < 4; mi++)
#pragma unroll
                    for (int ni = 0; ni < 4; ni++)
                        MMA_F16(cacc[mi][ni], a[mi], b[ni]);
            }
            __syncthreads();
        }

        // epilogue for this N-block: bias+relu -> h smem; s_logit partials
#pragma unroll
        for (int mi = 0; mi < 4; mi++) {
            int r0loc = warp_m * 64 + mi * 16 + (lane >> 2);
            float p00 = 0.f, p01 = 0.f, p10 = 0.f, p11 = 0.f;
#pragma unroll
            for (int ni = 0; ni < 4; ni++) {
                int lcol = warp_n * 32 + ni * 8 + 2 * (lane & 3);
                int gcol = bn + lcol;
                float b0 = bias[gcol], b1 = bias[gcol + 1];
                float v00 = fmaxf(cacc[mi][ni][0] + b0, 0.f);
                float v01 = fmaxf(cacc[mi][ni][1] + b1, 0.f);
                float v10 = fmaxf(cacc[mi][ni][2] + b0, 0.f);
                float v11 = fmaxf(cacc[mi][ni][3] + b1, 0.f);
                __half2 h0, h1;
                h0.x = __float2half_rn(v00); h0.y = __float2half_rn(v01);
                h1.x = __float2half_rn(v10); h1.y = __float2half_rn(v11);
                *(__half2*)&hsm[r0loc * HSTRIDE + gcol]       = h0;
                *(__half2*)&hsm[(r0loc + 8) * HSTRIDE + gcol] = h1;
                float2 w0 = Wp2[gcol], w1 = Wp2[gcol + 1];
                p00 += v00 * w0.x + v01 * w1.x;
                p01 += v00 * w0.y + v01 * w1.y;
                p10 += v10 * w0.x + v11 * w1.x;
                p11 += v10 * w0.y + v11 * w1.y;
            }
#pragma unroll
            for (int o = 1; o <= 2; o <<= 1) {
                p00 += __shfl_xor_sync(0xffffffffu, p00, o);
                p01 += __shfl_xor_sync(0xffffffffu, p01, o);
                p10 += __shfl_xor_sync(0xffffffffu, p10, o);
                p11 += __shfl_xor_sync(0xffffffffu, p11, o);
            }
            if ((lane & 3) == 0) {
                atomicAdd(&slacc[r0loc][0], p00);
                atomicAdd(&slacc[r0loc][1], p01);
                atomicAdd(&slacc[r0loc + 8][0], p10);
                atomicAdd(&slacc[r0loc + 8][1], p11);
            }
        }
    }
    __syncthreads();

    // softmax + per-graph stats
    int bgr = bm >> 12;
    if (tid < 128) {
        int node = bm + tid;
        float d0 = slacc[tid][0] + bp[0];
        float d1 = slacc[tid][1] + bp[1];
        dout[OUT_SLOG + node * 2]     = d0;
        dout[OUT_SLOG + node * 2 + 1] = d1;
        float m = fmaxf(d0, d1);
        float e0 = expf(d0 - m), e1 = expf(d1 - m);
        float inv = 1.f / (e0 + e1);
        float s0 = e0 * inv, s1 = e1 * inv;
        g_s[node * 2] = s0; g_s[node * 2 + 1] = s1;
        ssm[tid][0] = s0; ssm[tid][1] = s1;
        float dn = g_d[node];
        float ss00 = s0 * s0, ss01 = s0 * s1, ss11 = s1 * s1;
        float den = dn * (ss00 + ss11);
        ss00 = wredx(ss00); ss01 = wredx(ss01); ss11 = wredx(ss11); den = wredx(den);
        if (lane == 0) {
            atomicAdd(&g_accum[bgr * 4 + 0], ss00);
            atomicAdd(&g_accum[bgr * 4 + 1], ss01);
            atomicAdd(&g_accum[bgr * 4 + 2], ss11);
            atomicAdd(&g_accum[bgr * 4 + 3], den);
        }
    }
    __syncthreads();

    // pooled features: each thread owns 2 cols
    int f = tid * 2;
    float p0a = 0.f, p0b = 0.f, p1a = 0.f, p1b = 0.f;
#pragma unroll 4
    for (int r = 0; r < 128; r++) {
        __half2 hv = *(__half2*)&hsm[r * HSTRIDE + f];
        float2 hf = __half22float2(hv);
        float s0 = ssm[r][0], s1 = ssm[r][1];
        p0a += s0 * hf.x; p0b += s0 * hf.y;
        p1a += s1 * hf.x; p1b += s1 * hf.y;
    }
    atomicAdd(&g_out[bgr * 1024 + f],           p0a);
    atomicAdd(&g_out[bgr * 1024 + f + 1],       p0b);
    atomicAdd(&g_out[bgr * 1024 + 512 + f],     p1a);
    atomicAdd(&g_out[bgr * 1024 + 512 + f + 1], p1b);
}

// ---------------- out_adj[b,c,k] = sum_e s[src,c]*w*s[dst,k] ------------
__global__ void oa_kernel(const int* __restrict__ ei,
                          const float* __restrict__ ew) {
    __shared__ float red[8][4];
    int e = blockIdx.x * 256 + threadIdx.x;
    int src = ei[e];
    int dst = ei[NEDGE + e];
    float w = ew[e];
    float ss0 = g_s[src * 2], ss1 = g_s[src * 2 + 1];
    float sd0 = g_s[dst * 2], sd1 = g_s[dst * 2 + 1];
    float v00 = ss0 * w * sd0, v01 = ss0 * w * sd1;
    float v10 = ss1 * w * sd0, v11 = ss1 * w * sd1;
    v00 = wredx(v00); v01 = wredx(v01); v10 = wredx(v10); v11 = wredx(v11);
    int wip = threadIdx.x >> 5;
    if ((threadIdx.x & 31) == 0) {
        red[wip][0] = v00; red[wip][1] = v01; red[wip][2] = v10; red[wip][3] = v11;
    }
    __syncthreads();
    if (threadIdx.x < 4) {
        int b = src >> 12;
        float t = 0.f;
#pragma unroll
        for (int w2 = 0; w2 < 8; w2++) t += red[w2][threadIdx.x];
        atomicAdd(&g_oaraw[b * 4 + threadIdx.x], t);
    }
}

// ------- fused tail: finalize + xm + h2 + logits (1 block per graph) -----
__global__ __launch_bounds__(512) void tail_kernel(const float* __restrict__ Wrel3,
                                                   const float* __restrict__ brel3,
                                                   const float* __restrict__ Wroot3,
                                                   const float* __restrict__ Wlin1,
                                                   const float* __restrict__ blin1,
                                                   const float* __restrict__ Wlin2,
                                                   const float* __restrict__ blin2,
                                                   float* __restrict__ dout) {
    __shared__ float so0[512], so1[512], sxm[512], sh2[512];
    __shared__ float soan[2];
    __shared__ float lg[10];
    int b = blockIdx.x;
    int tid = threadIdx.x;

    if (tid == 0) {
        float a00 = g_oaraw[b * 4 + 0], a01 = g_oaraw[b * 4 + 1];
        float a10 = g_oaraw[b * 4 + 2], a11 = g_oaraw[b * 4 + 3];
        float num = a00 + a11;
        float den = g_accum[b * 4 + 3];
        float mc = -(num / den);
        float ss00 = g_accum[b * 4 + 0], ss01 = g_accum[b * 4 + 1], ss11 = g_accum[b * 4 + 2];
        float nrm = sqrtf(ss00 * ss00 + 2.f * ss01 * ss01 + ss11 * ss11);
        const float q = 0.70710678118654752f;
        float n00 = ss00 / nrm - q, n01 = ss01 / nrm, n11 = ss11 / nrm - q;
        float ol = sqrtf(n00 * n00 + 2.f * n01 * n01 + n11 * n11);
        float d2_0 = sqrtf(a01) + 1e-15f;
        float d2_1 = sqrtf(a10) + 1e-15f;
        float oa01 = a01 / (d2_0 * d2_1);
        float oa10 = a10 / (d2_1 * d2_0);
        soan[0] = oa01; soan[1] = oa10;
        dout[OUT_OA + b * 4 + 0] = 0.f;
        dout[OUT_OA + b * 4 + 1] = oa01;
        dout[OUT_OA + b * 4 + 2] = oa10;
        dout[OUT_OA + b * 4 + 3] = 0.f;
        atomicAdd(&dout[OUT_MC], mc / (float)NGR);
        atomicAdd(&dout[OUT_OL], ol / (float)NGR);
    }
    so0[tid] = g_out[(b * 2 + 0) * HID + tid];
    so1[tid] = g_out[(b * 2 + 1) * HID + tid];
    __syncthreads();

    float oa01 = soan[0], oa10 = soan[1];
    float acc = 0.f;
    for (int k = 0; k < HID; k++) {
        float u = oa10 * so1[k] + oa01 * so0[k];
        float v = so0[k] + so1[k];
        acc += u * Wrel3[k * HID + tid] + v * Wroot3[k * HID + tid];
    }
    sxm[tid] = 0.5f * acc + brel3[tid];
    __syncthreads();

    float acc2 = 0.f;
    for (int k = 0; k < HID; k++)
        acc2 += sxm[k] * Wlin1[k * HID + tid];
    sh2[tid] = fmaxf(acc2 + blin1[tid], 0.f);
    __syncthreads();

    if (tid < 320) {
        int o = tid >> 5, lane = tid & 31;
        float a = 0.f;
        for (int k = lane; k < HID; k += 32)
            a += sh2[k] * Wlin2[k * 10 + o];
        a = wredx(a);
        if (lane == 0) lg[o] = a + blin2[o];
    }
    __syncthreads();
    if (tid == 0) {
        float m = lg[0];
#pragma unroll
        for (int i = 1; i < 10; i++) m = fmaxf(m, lg[i]);
        float sum = 0.f;
#pragma unroll
        for (int i = 0; i < 10; i++) sum += expf(lg[i] - m);
        float lse = logf(sum) + m;
#pragma unroll
        for (int i = 0; i < 10; i++) dout[b * 10 + i] = lg[i] - lse;
    }
}

extern "C" void kernel_launch(void* const* d_in, const int* in_sizes, int n_in,
                              void* d_out, int out_size) {
    const float* x       = (const float*)d_in[0];
    const int*   ei      = (const int*)d_in[1];   // int32 (JAX x64 disabled)
    const float* ew      = (const float*)d_in[3];
    const float* W_rel1  = (const float*)d_in[4];
    const float* b_rel1  = (const float*)d_in[5];
    const float* W_root1 = (const float*)d_in[6];
    const float* W_pool  = (const float*)d_in[7];
    const float* b_pool  = (const float*)d_in[8];
    const float* W_rel3  = (const float*)d_in[9];
    const float* b_rel3  = (const float*)d_in[10];
    const float* W_root3 = (const float*)d_in[11];
    const float* W_lin1  = (const float*)d_in[12];
    const float* b_lin1  = (const float*)d_in[13];
    const float* W_lin2  = (const float*)d_in[14];
    const float* b_lin2  = (const float*)d_in[15];
    float* out = (float*)d_out;

    static int smem_set = 0;
    if (!smem_set) {
        cudaFuncSetAttribute(gemm_mega, cudaFuncAttributeMaxDynamicSharedMemorySize,
                             GB_SMEM);
        smem_set = 1;
    }

    zero_kernel<<<129, 256>>>(out);
    prep_kernel<<<5632, 256>>>(x, W_rel1, W_root1, ei, ew);
    scanA_kernel<<<128, 256>>>();
    scanC_kernel<<<128, 256>>>();
    scatter_kernel<<<NEDGE / 512, 256>>>(ei, ew);
    agg_kernel<<<NNODE / 8, 256>>>();
    gemm_mega<<<NNODE / 128, 256, GB_SMEM>>>(b_rel1, W_pool, b_pool, out);
    oa_kernel<<<NEDGE / 256, 256>>>(ei, ew);
    tail_kernel<<<NGR, 512>>>(W_rel3, b_rel3, W_root3, W_lin1, b_lin1,
                              W_lin2, b_lin2, out);
}

// round 15
// speedup vs baseline: 2.4145x; 1.6735x over previous
#include <cuda_runtime.h>
#include <cuda_fp16.h>
#include <math.h>
#include <stdint.h>

#define NEDGE 524288
#define NNODE 32768
#define NGR   8
#define NLOC  4096
#define FIN   128
#define HID   512

#define OUT_MC    80
#define OUT_OL    81
#define OUT_SLOG  82
#define OUT_OA    65618

// ---- scratch ----
__device__ __half g_Ah[NNODE * 256];     // [fp16(agg)(128) | fp16(x)(128)]
__device__ __half g_Bh[512 * 256];       // Bh[n][k]: fp16(W=[W1;W2]), K=256
__device__ float g_s[NNODE * 2];
__device__ int   g_cnt[NNODE];
__device__ int   g_offs[NNODE + 1];
__device__ int   g_cursor[NNODE];
__device__ int   g_bsum[128];
__device__ float2 g_edge[NEDGE];         // sorted {src(bits), w}
__device__ float g_d[NNODE];
__device__ float g_accum[NGR * 4];
__device__ float g_oaraw[NGR * 4];
__device__ float g_out[NGR * 2 * HID];

__device__ __forceinline__ float wredx(float v) {
#pragma unroll
    for (int o = 16; o; o >>= 1) v += __shfl_xor_sync(0xffffffffu, v, o);
    return v;
}
__device__ __forceinline__ int iredx(int v) {
#pragma unroll
    for (int o = 16; o; o >>= 1) v += __shfl_xor_sync(0xffffffffu, v, o);
    return v;
}

#define SMEM_SWZ(o) ((o) ^ (((o) >> 3) & 0x70))

__device__ __forceinline__ uint32_t smem_u32(const void* p) {
    return (uint32_t)__cvta_generic_to_shared(p);
}
__device__ __forceinline__ void cp16s(uint32_t saddr, const void* g) {
    asm volatile("cp.async.cg.shared.global [%0], [%1], 16;"
                 :: "r"(saddr), "l"(g) : "memory");
}
__device__ __forceinline__ void ldsm4(uint32_t* r, uint32_t a) {
    asm volatile("ldmatrix.sync.aligned.m8n8.x4.shared.b16 {%0,%1,%2,%3}, [%4];"
                 : "=r"(r[0]), "=r"(r[1]), "=r"(r[2]), "=r"(r[3]) : "r"(a));
}
__device__ __forceinline__ void ldsm2(uint32_t* r, uint32_t a) {
    asm volatile("ldmatrix.sync.aligned.m8n8.x2.shared.b16 {%0,%1}, [%2];"
                 : "=r"(r[0]), "=r"(r[1]) : "r"(a));
}
#define MMA_F16(d, a, b)                                                      \
    asm volatile(                                                             \
        "mma.sync.aligned.m16n8k16.row.col.f32.f16.f16.f32 "                  \
        "{%0,%1,%2,%3},{%4,%5,%6,%7},{%8,%9},{%0,%1,%2,%3};"                  \
        : "+f"((d)[0]), "+f"((d)[1]), "+f"((d)[2]), "+f"((d)[3])              \
        : "r"((a)[0]), "r"((a)[1]), "r"((a)[2]), "r"((a)[3]),                 \
          "r"((b)[0]), "r"((b)[1]))

// ---------------- zero scratch ----------------
__global__ void zero_kernel(float* __restrict__ dout) {
    int i = blockIdx.x * 256 + threadIdx.x;
    if (i < NNODE) g_cnt[i] = 0;
    if (i < NNODE) g_d[i] = 0.f;
    if (i < NGR * 2 * HID) g_out[i] = 0.f;
    if (i < NGR * 4) { g_accum[i] = 0.f; g_oaraw[i] = 0.f; }
    if (i < 2) dout[OUT_MC + i] = 0.f;
}

// --- fused prep: cvtX (0-2047) | cvtB (2048-2559) | count (2560-3583) ---
__global__ void prep_kernel(const float* __restrict__ x,
                            const float* __restrict__ W1,
                            const float* __restrict__ W2,
                            const int* __restrict__ ei,
                            const float* __restrict__ ew) {
    int blk = blockIdx.x;
    if (blk < 2048) {
        // x -> fp16 into A_ext cols [128,256)
        int idx = blk * 256 + threadIdx.x;   // 32768*16 uint4-ish units of 8 floats
        int row = idx >> 4;
        int c8  = (idx & 15) * 8;
        float4 v0 = *(const float4*)&x[(size_t)row * 128 + c8];
        float4 v1 = *(const float4*)&x[(size_t)row * 128 + c8 + 4];
        __half h[8];
        h[0] = __float2half_rn(v0.x); h[1] = __float2half_rn(v0.y);
        h[2] = __float2half_rn(v0.z); h[3] = __float2half_rn(v0.w);
        h[4] = __float2half_rn(v1.x); h[5] = __float2half_rn(v1.y);
        h[6] = __float2half_rn(v1.z); h[7] = __float2half_rn(v1.w);
        *(uint4*)&g_Ah[(size_t)row * 256 + 128 + c8] = *(uint4*)h;
    } else if (blk < 2560) {
        int idx = (blk - 2048) * 256 + threadIdx.x;
        int n = idx >> 8;
        int r = idx & 255;
        float v = (r < 128) ? W1[(size_t)r * 512 + n]
                            : W2[(size_t)(r - 128) * 512 + n];
        g_Bh[(size_t)n * 256 + r] = __float2half_rn(v);
    } else {
        int g = (blk - 2560) * 256 + threadIdx.x;
        int e = g * 2;
        if (e >= NEDGE) return;
        int2   s2 = *(const int2*)&ei[e];
        int2   d2 = *(const int2*)&ei[NEDGE + e];
        float2 w2 = *(const float2*)&ew[e];
        atomicAdd(&g_cnt[d2.x], 1);
        atomicAdd(&g_cnt[d2.y], 1);
        atomicAdd(&g_d[s2.x], w2.x);
        atomicAdd(&g_d[s2.y], w2.y);
    }
}

// ---------------- scan phase A: 128 blocks, local exclusive scan --------
__global__ void scanA_kernel() {
    __shared__ int sm[256];
    int tid = threadIdx.x;
    int idx = blockIdx.x * 256 + tid;
    int v = g_cnt[idx];
    sm[tid] = v;
    __syncthreads();
#pragma unroll
    for (int o = 1; o < 256; o <<= 1) {
        int t = (tid >= o) ? sm[tid - o] : 0;
        __syncthreads();
        sm[tid] += t;
        __syncthreads();
    }
    int incl = sm[tid];
    g_offs[idx] = incl - v;
    if (tid == 255) g_bsum[blockIdx.x] = incl;
}

// ---------------- scan phase C: add block offsets, write cursor ---------
__global__ void scanC_kernel() {
    __shared__ int soff;
    int tid = threadIdx.x;
    int blk = blockIdx.x;
    if (tid < 32) {
        int s = 0;
        for (int j = tid; j < blk; j += 32) s += g_bsum[j];
        s = iredx(s);
        if (tid == 0) soff = s;
    }
    __syncthreads();
    int idx = blk * 256 + tid;
    int val = g_offs[idx] + soff;
    g_offs[idx] = val;
    g_cursor[idx] = val;
    if (blk == 0 && tid == 0) g_offs[NNODE] = NEDGE;
}

// ---------------- scatter edges sorted by dst (2 edges/thread) ----------
__global__ void scatter_kernel(const int* __restrict__ ei,
                               const float* __restrict__ ew) {
    int g = blockIdx.x * 256 + threadIdx.x;
    int e = g * 2;
    if (e >= NEDGE) return;
    int2   s2 = *(const int2*)&ei[e];
    int2   d2 = *(const int2*)&ei[NEDGE + e];
    float2 w2 = *(const float2*)&ew[e];
    int p0 = atomicAdd(&g_cursor[d2.x], 1);
    int p1 = atomicAdd(&g_cursor[d2.y], 1);
    g_edge[p0] = make_float2(__int_as_float(s2.x), w2.x);
    g_edge[p1] = make_float2(__int_as_float(s2.y), w2.y);
}

// --------- agg: gather fp16 x from A_ext x-half, write agg fp16 ----------
__global__ void agg_kernel() {
    int gwarp = (blockIdx.x * 256 + threadIdx.x) >> 5;
    int lane  = threadIdx.x & 31;
    int s0 = g_offs[gwarp], s1 = g_offs[gwarp + 1];
    const uint2* xh = (const uint2*)g_Ah;   // row stride 64 uint2; x at +32
    float4 acc = make_float4(0.f, 0.f, 0.f, 0.f);
    int e = s0;
    for (; e + 4 <= s1; e += 4) {
        float2 e0 = g_edge[e],     e1 = g_edge[e + 1];
        float2 e2 = g_edge[e + 2], e3 = g_edge[e + 3];
        uint2 u0 = xh[__float_as_int(e0.x) * 64 + 32 + lane];
        uint2 u1 = xh[__float_as_int(e1.x) * 64 + 32 + lane];
        uint2 u2 = xh[__float_as_int(e2.x) * 64 + 32 + lane];
        uint2 u3 = xh[__float_as_int(e3.x) * 64 + 32 + lane];
        float2 a0 = __half22float2(*(__half2*)&u0.x), b0 = __half22float2(*(__half2*)&u0.y);
        float2 a1 = __half22float2(*(__half2*)&u1.x), b1 = __half22float2(*(__half2*)&u1.y);
        float2 a2 = __half22float2(*(__half2*)&u2.x), b2 = __half22float2(*(__half2*)&u2.y);
        float2 a3 = __half22float2(*(__half2*)&u3.x), b3 = __half22float2(*(__half2*)&u3.y);
        acc.x += e0.y * a0.x; acc.y += e0.y * a0.y; acc.z += e0.y * b0.x; acc.w += e0.y * b0.y;
        acc.x += e1.y * a1.x; acc.y += e1.y * a1.y; acc.z += e1.y * b1.x; acc.w += e1.y * b1.y;
        acc.x += e2.y * a2.x; acc.y += e2.y * a2.y; acc.z += e2.y * b2.x; acc.w += e2.y * b2.y;
        acc.x += e3.y * a3.x; acc.y += e3.y * a3.y; acc.z += e3.y * b3.x; acc.w += e3.y * b3.y;
    }
    for (; e < s1; e++) {
        float2 ee = g_edge[e];
        uint2 u = xh[__float_as_int(ee.x) * 64 + 32 + lane];
        float2 a = __half22float2(*(__half2*)&u.x), b = __half22float2(*(__half2*)&u.y);
        acc.x += ee.y * a.x; acc.y += ee.y * a.y; acc.z += ee.y * b.x; acc.w += ee.y * b.y;
    }
    __half h[4];
    h[0] = __float2half_rn(acc.x);
    h[1] = __float2half_rn(acc.y);
    h[2] = __float2half_rn(acc.z);
    h[3] = __float2half_rn(acc.w);
    *(uint2*)&g_Ah[(size_t)gwarp * 256 + lane * 4] = *(uint2*)h;
}

// ===== mega GEMM: K=256 (4 stages); h in smem; fused softmax/stats/pool ==
#define HSTRIDE 520
#define HS_BYTES (128 * HSTRIDE * 2)
#define GB_SMEM (HS_BYTES + 65536)

__global__ __launch_bounds__(256) void gemm_mega(const float* __restrict__ bias,
                                                 const float* __restrict__ Wp,
                                                 const float* __restrict__ bp,
                                                 float* __restrict__ dout) {
    extern __shared__ char dsm[];
    __half* hsm = (__half*)dsm;
    uint32_t base = smem_u32(dsm);
    uint32_t Ao[2] = { base + HS_BYTES,         base + HS_BYTES + 16384 };
    uint32_t Bo[2] = { base + HS_BYTES + 32768, base + HS_BYTES + 49152 };
    __shared__ float slacc[128][2];
    __shared__ float ssm[128][2];

    int tid  = threadIdx.x;
    int lane = tid & 31;
    int wid  = tid >> 5;
    int warp_m = wid & 1;
    int warp_n = wid >> 1;
    int bm = blockIdx.x * 128;

    if (tid < 128) { slacc[tid][0] = 0.f; slacc[tid][1] = 0.f; }

    int a_row  = warp_m * 64 + (lane & 15);
    int a_csel = ((lane >> 4) & 1) * 16;
    int b_row  = warp_n * 32 + (lane & 7);
    int b_csel = (lane & 8) ? 16 : 0;

    const float2* Wp2 = (const float2*)Wp;

    for (int nb = 0; nb < 4; nb++) {
        int bn = nb * 128;
        float cacc[4][4][4];
#pragma unroll
        for (int i = 0; i < 4; i++)
#pragma unroll
            for (int j = 0; j < 4; j++)
#pragma unroll
                for (int r = 0; r < 4; r++) cacc[i][j][r] = 0.f;

        auto load_stage = [&](int s, int buf) {
            int kk = s << 6;
#pragma unroll
            for (int t = 0; t < 4; t++) {
                int id  = tid + t * 256;
                int r   = id >> 3;
                int c16 = id & 7;
                uint32_t off = SMEM_SWZ((uint32_t)(r * 128 + c16 * 16));
                cp16s(Ao[buf] + off, &g_Ah[(size_t)(bm + r) * 256 + kk + c16 * 8]);
            }
#pragma unroll
            for (int t = 0; t < 4; t++) {
                int id  = tid + t * 256;
                int r   = id >> 3;
                int c16 = id & 7;
                uint32_t off = SMEM_SWZ((uint32_t)(r * 128 + c16 * 16));
                cp16s(Bo[buf] + off, &g_Bh[(size_t)(bn + r) * 256 + kk + c16 * 8]);
            }
            asm volatile("cp.async.commit_group;" ::: "memory");
        };

        load_stage(0, 0);
        for (int s = 0; s < 4; s++) {
            if (s < 3) {
                load_stage(s + 1, (s + 1) & 1);
                asm volatile("cp.async.wait_group 1;" ::: "memory");
            } else {
                asm volatile("cp.async.wait_group 0;" ::: "memory");
            }
            __syncthreads();
            uint32_t As = Ao[s & 1];
            uint32_t Bs = Bo[s & 1];
#pragma unroll
            for (int k = 0; k < 4; k++) {
                int kbA = k * 32 + a_csel;
                int kbB = k * 32 + b_csel;
                uint32_t a[4][4], b[4][2];
#pragma unroll
                for (int mi = 0; mi < 4; mi++) {
                    uint32_t addr = As + SMEM_SWZ((uint32_t)((a_row + mi * 16) * 128 + kbA));
                    ldsm4(a[mi], addr);
                }
#pragma unroll
                for (int ni = 0; ni < 4; ni++) {
                    uint32_t addr = Bs + SMEM_SWZ((uint32_t)((b_row + ni * 8) * 128 + kbB));
                    ldsm2(b[ni], addr);
                }
#pragma unroll
                for (int mi = 0; mi < 4; mi++)
#pragma unroll
                    for (int ni = 0; ni < 4; ni++)
                        MMA_F16(cacc[mi][ni], a[mi], b[ni]);
            }
            __syncthreads();
        }

        // epilogue: bias+relu -> h smem; s_logit partials
#pragma unroll
        for (int mi = 0; mi < 4; mi++) {
            int r0loc = warp_m * 64 + mi * 16 + (lane >> 2);
            float p00 = 0.f, p01 = 0.f, p10 = 0.f, p11 = 0.f;
#pragma unroll
            for (int ni = 0; ni < 4; ni++) {
                int gcol = bn + warp_n * 32 + ni * 8 + 2 * (lane & 3);
                float b0 = bias[gcol], b1 = bias[gcol + 1];
                float v00 = fmaxf(cacc[mi][ni][0] + b0, 0.f);
                float v01 = fmaxf(cacc[mi][ni][1] + b1, 0.f);
                float v10 = fmaxf(cacc[mi][ni][2] + b0, 0.f);
                float v11 = fmaxf(cacc[mi][ni][3] + b1, 0.f);
                __half2 h0, h1;
                h0.x = __float2half_rn(v00); h0.y = __float2half_rn(v01);
                h1.x = __float2half_rn(v10); h1.y = __float2half_rn(v11);
                *(__half2*)&hsm[r0loc * HSTRIDE + gcol]       = h0;
                *(__half2*)&hsm[(r0loc + 8) * HSTRIDE + gcol] = h1;
                float2 w0 = Wp2[gcol], w1 = Wp2[gcol + 1];
                p00 += v00 * w0.x + v01 * w1.x;
                p01 += v00 * w0.y + v01 * w1.y;
                p10 += v10 * w0.x + v11 * w1.x;
                p11 += v10 * w0.y + v11 * w1.y;
            }
#pragma unroll
            for (int o = 1; o <= 2; o <<= 1) {
                p00 += __shfl_xor_sync(0xffffffffu, p00, o);
                p01 += __shfl_xor_sync(0xffffffffu, p01, o);
                p10 += __shfl_xor_sync(0xffffffffu, p10, o);
                p11 += __shfl_xor_sync(0xffffffffu, p11, o);
            }
            if ((lane & 3) == 0) {
                atomicAdd(&slacc[r0loc][0], p00);
                atomicAdd(&slacc[r0loc][1], p01);
                atomicAdd(&slacc[r0loc + 8][0], p10);
                atomicAdd(&slacc[r0loc + 8][1], p11);
            }
        }
    }
    __syncthreads();

    // softmax + per-graph stats
    int bgr = bm >> 12;
    if (tid < 128) {
        int node = bm + tid;
        float d0 = slacc[tid][0] + bp[0];
        float d1 = slacc[tid][1] + bp[1];
        dout[OUT_SLOG + node * 2]     = d0;
        dout[OUT_SLOG + node * 2 + 1] = d1;
        float m = fmaxf(d0, d1);
        float e0 = expf(d0 - m), e1 = expf(d1 - m);
        float inv = 1.f / (e0 + e1);
        float s0 = e0 * inv, s1 = e1 * inv;
        g_s[node * 2] = s0; g_s[node * 2 + 1] = s1;
        ssm[tid][0] = s0; ssm[tid][1] = s1;
        float dn = g_d[node];
        float ss00 = s0 * s0, ss01 = s0 * s1, ss11 = s1 * s1;
        float den = dn * (ss00 + ss11);
        ss00 = wredx(ss00); ss01 = wredx(ss01); ss11 = wredx(ss11); den = wredx(den);
        if (lane == 0) {
            atomicAdd(&g_accum[bgr * 4 + 0], ss00);
            atomicAdd(&g_accum[bgr * 4 + 1], ss01);
            atomicAdd(&g_accum[bgr * 4 + 2], ss11);
            atomicAdd(&g_accum[bgr * 4 + 3], den);
        }
    }
    __syncthreads();

    // pooled features: each thread owns 2 cols
    int f = tid * 2;
    float p0a = 0.f, p0b = 0.f, p1a = 0.f, p1b = 0.f;
#pragma unroll 4
    for (int r = 0; r < 128; r++) {
        __half2 hv = *(__half2*)&hsm[r * HSTRIDE + f];
        float2 hf = __half22float2(hv);
        float s0 = ssm[r][0], s1 = ssm[r][1];
        p0a += s0 * hf.x; p0b += s0 * hf.y;
        p1a += s1 * hf.x; p1b += s1 * hf.y;
    }
    atomicAdd(&g_out[bgr * 1024 + f],           p0a);
    atomicAdd(&g_out[bgr * 1024 + f + 1],       p0b);
    atomicAdd(&g_out[bgr * 1024 + 512 + f],     p1a);
    atomicAdd(&g_out[bgr * 1024 + 512 + f + 1], p1b);
}

// ---------------- out_adj[b,c,k] = sum_e s[src,c]*w*s[dst,k] ------------
__global__ void oa_kernel(const int* __restrict__ ei,
                          const float* __restrict__ ew) {
    __shared__ float red[8][4];
    int e = blockIdx.x * 256 + threadIdx.x;
    int src = ei[e];
    int dst = ei[NEDGE + e];
    float w = ew[e];
    float ss0 = g_s[src * 2], ss1 = g_s[src * 2 + 1];
    float sd0 = g_s[dst * 2], sd1 = g_s[dst * 2 + 1];
    float v00 = ss0 * w * sd0, v01 = ss0 * w * sd1;
    float v10 = ss1 * w * sd0, v11 = ss1 * w * sd1;
    v00 = wredx(v00); v01 = wredx(v01); v10 = wredx(v10); v11 = wredx(v11);
    int wip = threadIdx.x >> 5;
    if ((threadIdx.x & 31) == 0) {
        red[wip][0] = v00; red[wip][1] = v01; red[wip][2] = v10; red[wip][3] = v11;
    }
    __syncthreads();
    if (threadIdx.x < 4) {
        int b = src >> 12;
        float t = 0.f;
#pragma unroll
        for (int w2 = 0; w2 < 8; w2++) t += red[w2][threadIdx.x];
        atomicAdd(&g_oaraw[b * 4 + threadIdx.x], t);
    }
}

// ------- fused tail: finalize + xm + h2 + logits (1 block per graph) -----
__global__ __launch_bounds__(512) void tail_kernel(const float* __restrict__ Wrel3,
                                                   const float* __restrict__ brel3,
                                                   const float* __restrict__ Wroot3,
                                                   const float* __restrict__ Wlin1,
                                                   const float* __restrict__ blin1,
                                                   const float* __restrict__ Wlin2,
                                                   const float* __restrict__ blin2,
                                                   float* __restrict__ dout) {
    __shared__ float so0[512], so1[512], sxm[512], sh2[512];
    __shared__ float soan[2];
    __shared__ float lg[10];
    int b = blockIdx.x;
    int tid = threadIdx.x;

    if (tid == 0) {
        float a00 = g_oaraw[b * 4 + 0], a01 = g_oaraw[b * 4 + 1];
        float a10 = g_oaraw[b * 4 + 2], a11 = g_oaraw[b * 4 + 3];
        float num = a00 + a11;
        float den = g_accum[b * 4 + 3];
        float mc = -(num / den);
        float ss00 = g_accum[b * 4 + 0], ss01 = g_accum[b * 4 + 1], ss11 = g_accum[b * 4 + 2];
        float nrm = sqrtf(ss00 * ss00 + 2.f * ss01 * ss01 + ss11 * ss11);
        const float q = 0.70710678118654752f;
        float n00 = ss00 / nrm - q, n01 = ss01 / nrm, n11 = ss11 / nrm - q;
        float ol = sqrtf(n00 * n00 + 2.f * n01 * n01 + n11 * n11);
        float d2_0 = sqrtf(a01) + 1e-15f;
        float d2_1 = sqrtf(a10) + 1e-15f;
        float oa01 = a01 / (d2_0 * d2_1);
        float oa10 = a10 / (d2_1 * d2_0);
        soan[0] = oa01; soan[1] = oa10;
        dout[OUT_OA + b * 4 + 0] = 0.f;
        dout[OUT_OA + b * 4 + 1] = oa01;
        dout[OUT_OA + b * 4 + 2] = oa10;
        dout[OUT_OA + b * 4 + 3] = 0.f;
        atomicAdd(&dout[OUT_MC], mc / (float)NGR);
        atomicAdd(&dout[OUT_OL], ol / (float)NGR);
    }
    so0[tid] = g_out[(b * 2 + 0) * HID + tid];
    so1[tid] = g_out[(b * 2 + 1) * HID + tid];
    __syncthreads();

    float oa01 = soan[0], oa10 = soan[1];
    float acc = 0.f;
    for (int k = 0; k < HID; k++) {
        float u = oa10 * so1[k] + oa01 * so0[k];
        float v = so0[k] + so1[k];
        acc += u * Wrel3[k * HID + tid] + v * Wroot3[k * HID + tid];
    }
    sxm[tid] = 0.5f * acc + brel3[tid];
    __syncthreads();

    float acc2 = 0.f;
    for (int k = 0; k < HID; k++)
        acc2 += sxm[k] * Wlin1[k * HID + tid];
    sh2[tid] = fmaxf(acc2 + blin1[tid], 0.f);
    __syncthreads();

    if (tid < 320) {
        int o = tid >> 5, lane = tid & 31;
        float a = 0.f;
        for (int k = lane; k < HID; k += 32)
            a += sh2[k] * Wlin2[k * 10 + o];
        a = wredx(a);
        if (lane == 0) lg[o] = a + blin2[o];
    }
    __syncthreads();
    if (tid == 0) {
        float m = lg[0];
#pragma unroll
        for (int i = 1; i < 10; i++) m = fmaxf(m, lg[i]);
        float sum = 0.f;
#pragma unroll
        for (int i = 0; i < 10; i++) sum += expf(lg[i] - m);
        float lse = logf(sum) + m;
#pragma unroll
        for (int i = 0; i < 10; i++) dout[b * 10 + i] = lg[i] - lse;
    }
}

extern "C" void kernel_launch(void* const* d_in, const int* in_sizes, int n_in,
                              void* d_out, int out_size) {
    const float* x       = (const float*)d_in[0];
    const int*   ei      = (const int*)d_in[1];   // int32 (JAX x64 disabled)
    const float* ew      = (const float*)d_in[3];
    const float* W_rel1  = (const float*)d_in[4];
    const float* b_rel1  = (const float*)d_in[5];
    const float* W_root1 = (const float*)d_in[6];
    const float* W_pool  = (const float*)d_in[7];
    const float* b_pool  = (const float*)d_in[8];
    const float* W_rel3  = (const float*)d_in[9];
    const float* b_rel3  = (const float*)d_in[10];
    const float* W_root3 = (const float*)d_in[11];
    const float* W_lin1  = (const float*)d_in[12];
    const float* b_lin1  = (const float*)d_in[13];
    const float* W_lin2  = (const float*)d_in[14];
    const float* b_lin2  = (const float*)d_in[15];
    float* out = (float*)d_out;

    static int smem_set = 0;
    if (!smem_set) {
        cudaFuncSetAttribute(gemm_mega, cudaFuncAttributeMaxDynamicSharedMemorySize,
                             GB_SMEM);
        smem_set = 1;
    }

    zero_kernel<<<129, 256>>>(out);
    prep_kernel<<<3584, 256>>>(x, W_rel1, W_root1, ei, ew);
    scanA_kernel<<<128, 256>>>();
    scanC_kernel<<<128, 256>>>();
    scatter_kernel<<<NEDGE / 512, 256>>>(ei, ew);
    agg_kernel<<<NNODE / 8, 256>>>();
    gemm_mega<<<NNODE / 128, 256, GB_SMEM>>>(b_rel1, W_pool, b_pool, out);
    oa_kernel<<<NEDGE / 256, 256>>>(ei, ew);
    tail_kernel<<<NGR, 512>>>(W_rel3, b_rel3, W_root3, W_lin1, b_lin1,
                              W_lin2, b_lin2, out);
}